// round 8
// baseline (speedup 1.0000x reference)
#include <cuda_runtime.h>
#include <cuda_bf16.h>
#include <cstdint>
#include <math.h>

#define N_TOK 4096
#define DDIM  512
#define KEEP  2048

// ---------------- device scratch (uint4 for 16B alignment) ----------------
__device__ uint4 g_xhi [N_TOK * DDIM / 8];
__device__ uint4 g_xlo [N_TOK * DDIM / 8];
__device__ uint4 g_WThi[3 * DDIM * DDIM / 8];
__device__ uint4 g_WTlo[3 * DDIM * DDIM / 8];
__device__ uint4 g_qhi [N_TOK * DDIM / 8];
__device__ uint4 g_qlo [N_TOK * DDIM / 8];
__device__ uint4 g_kThi[N_TOK * DDIM / 8];
__device__ uint4 g_kTlo[N_TOK * DDIM / 8];
__device__ uint4 g_vThi[N_TOK * DDIM / 8];
__device__ uint4 g_vTlo[N_TOK * DDIM / 8];
__device__ uint4 g_atthi[(size_t)N_TOK * N_TOK / 8];
__device__ uint4 g_attlo[(size_t)N_TOK * N_TOK / 8];
__device__ float g_k[N_TOK * DDIM];
__device__ float g_v[N_TOK * DDIM];
__device__ float g_score[(size_t)N_TOK * N_TOK];
__device__ float g_part[4][N_TOK * DDIM];

typedef __nv_bfloat16 bf16;

// ---------------- helpers ----------------
__device__ __forceinline__ uint32_t smem_u32(const void* p) {
    uint32_t a;
    asm("{ .reg .u64 t; cvta.to.shared.u64 t, %1; cvt.u32.u64 %0, t; }"
        : "=r"(a) : "l"(p));
    return a;
}
__device__ __forceinline__ void split_bf(float f, bf16& h, bf16& l) {
    h = __float2bfloat16_rn(f);
    l = __float2bfloat16_rn(f - __bfloat162float(h));
}

#define CP16(dst, src) \
    asm volatile("cp.async.cg.shared.global [%0], [%1], 16;" :: "r"(dst), "l"(src) : "memory")
#define CP_COMMIT() asm volatile("cp.async.commit_group;" ::: "memory")
#define CP_WAIT1()  asm volatile("cp.async.wait_group 1;" ::: "memory")
#define CP_WAIT0()  asm volatile("cp.async.wait_group 0;" ::: "memory")

#define LDSM4(r, a)                                                             \
    asm volatile("ldmatrix.sync.aligned.m8n8.x4.shared.b16 {%0,%1,%2,%3}, [%4];" \
        : "=r"((r)[0]), "=r"((r)[1]), "=r"((r)[2]), "=r"((r)[3]) : "r"(a))

// m16n8k16 bf16 MMA, D += A*B (row.col), f32 accumulate
#define MMA16(cc, a, b)                                                         \
    asm volatile("mma.sync.aligned.m16n8k16.row.col.f32.bf16.bf16.f32 "         \
        "{%0,%1,%2,%3}, {%4,%5,%6,%7}, {%8,%9}, {%0,%1,%2,%3};"                 \
        : "+f"((cc)[0]), "+f"((cc)[1]), "+f"((cc)[2]), "+f"((cc)[3])            \
        : "r"((a)[0]), "r"((a)[1]), "r"((a)[2]), "r"((a)[3]),                   \
          "r"((b)[0]), "r"((b)[1]))

// ---------------------------------------------------------------------------
// 3xBF16 mma.sync GEMM body (unchanged from R7): C = scale*(A @ B^T) (+bias)
// ---------------------------------------------------------------------------
#define TILE_B    18432                    // 128 * 144
#define STAGE_ALL (4 * TILE_B)             // 73728
#define GEMM_SMEM_BYTES (2 * STAGE_ALL)    // 147456

template<bool BIAS, bool SPLIT_OUT>
__device__ __forceinline__ void gemm_body(
    const bf16* __restrict__ Ahi, const bf16* __restrict__ Alo, int lda,
    const bf16* __restrict__ Bhi, const bf16* __restrict__ Blo, int ldb,
    float* __restrict__ C, bf16* __restrict__ Chi, bf16* __restrict__ Clo, int ldc,
    int K, const float* __restrict__ bias, float scale,
    int bx, int by, char* sm)
{
    const uint32_t smb = smem_u32(sm);

    const int tid  = threadIdx.x;
    const int w    = tid >> 5;
    const int lane = tid & 31;
    const int wm   = w & 3;
    const int wn   = w >> 2;
    const int g    = lane >> 2;
    const int tig  = lane & 3;

    const int lrow = tid >> 2;
    const int lch  = tid & 3;
    const bf16* pAh = Ahi + (size_t)(by * 128 + lrow) * lda + lch * 16;
    const bf16* pAl = Alo + (size_t)(by * 128 + lrow) * lda + lch * 16;
    const bf16* pBh = Bhi + (size_t)(bx * 128 + lrow) * ldb + lch * 16;
    const bf16* pBl = Blo + (size_t)(bx * 128 + lrow) * ldb + lch * 16;
    const uint32_t so = (uint32_t)lrow * 144 + lch * 32;

    const int l7 = lane & 7;
    const uint32_t aoff0 = (uint32_t)(wm * 32 + ((lane >> 3) & 1) * 8 + l7) * 144
                         + (uint32_t)(lane >> 4) * 16;
    const uint32_t aoff1 = aoff0 + 16u * 144u;
    const uint32_t boff0 = 2u * TILE_B
                         + (uint32_t)(wn * 32 + (lane >> 4) * 8 + l7) * 144
                         + (uint32_t)((lane >> 3) & 1) * 16;
    const uint32_t boff1 = boff0 + 16u * 144u;

    float c[2][4][4] = {};
    const int nT = K >> 6;

    {
        const uint32_t st = smb;
        CP16(st + so,                   pAh);
        CP16(st + so + 16,              pAh + 8);
        CP16(st + TILE_B + so,          pAl);
        CP16(st + TILE_B + so + 16,     pAl + 8);
        CP16(st + 2 * TILE_B + so,      pBh);
        CP16(st + 2 * TILE_B + so + 16, pBh + 8);
        CP16(st + 3 * TILE_B + so,      pBl);
        CP16(st + 3 * TILE_B + so + 16, pBl + 8);
        CP_COMMIT();
    }

    for (int kt = 0; kt < nT; ++kt) {
        if (kt + 1 < nT) {
            const uint32_t st = smb + ((kt + 1) & 1) * STAGE_ALL;
            const int ko = (kt + 1) * 64;
            CP16(st + so,                   pAh + ko);
            CP16(st + so + 16,              pAh + ko + 8);
            CP16(st + TILE_B + so,          pAl + ko);
            CP16(st + TILE_B + so + 16,     pAl + ko + 8);
            CP16(st + 2 * TILE_B + so,      pBh + ko);
            CP16(st + 2 * TILE_B + so + 16, pBh + ko + 8);
            CP16(st + 3 * TILE_B + so,      pBl + ko);
            CP16(st + 3 * TILE_B + so + 16, pBl + ko + 8);
            CP_COMMIT();
            CP_WAIT1();
        } else {
            CP_WAIT0();
        }
        __syncthreads();

        const uint32_t stb = smb + (kt & 1) * STAGE_ALL;

        #pragma unroll
        for (int ks = 0; ks < 4; ++ks) {
            const uint32_t koff = (uint32_t)ks * 32;

            uint32_t ah[2][4], al[2][4], bh[2][4], bl[2][4];
            LDSM4(ah[0], stb + aoff0 + koff);
            LDSM4(ah[1], stb + aoff1 + koff);
            LDSM4(bh[0], stb + boff0 + koff);
            LDSM4(bh[1], stb + boff1 + koff);
            LDSM4(al[0], stb + TILE_B + aoff0 + koff);
            LDSM4(al[1], stb + TILE_B + aoff1 + koff);
            LDSM4(bl[0], stb + TILE_B + boff0 + koff);
            LDSM4(bl[1], stb + TILE_B + boff1 + koff);

            #pragma unroll
            for (int mi = 0; mi < 2; ++mi)
                #pragma unroll
                for (int ni = 0; ni < 4; ++ni)
                    MMA16(c[mi][ni], ah[mi], bh[ni >> 1] + (ni & 1) * 2);
            #pragma unroll
            for (int mi = 0; mi < 2; ++mi)
                #pragma unroll
                for (int ni = 0; ni < 4; ++ni)
                    MMA16(c[mi][ni], al[mi], bh[ni >> 1] + (ni & 1) * 2);
            #pragma unroll
            for (int mi = 0; mi < 2; ++mi)
                #pragma unroll
                for (int ni = 0; ni < 4; ++ni)
                    MMA16(c[mi][ni], ah[mi], bl[ni >> 1] + (ni & 1) * 2);
        }
        __syncthreads();
    }

    #pragma unroll
    for (int mi = 0; mi < 2; ++mi) {
        const int r0 = by * 128 + wm * 32 + mi * 16 + g;
        #pragma unroll
        for (int ni = 0; ni < 4; ++ni) {
            const int col = bx * 128 + wn * 32 + ni * 8 + tig * 2;
            float vv[4];
            vv[0] = c[mi][ni][0] * scale; vv[1] = c[mi][ni][1] * scale;
            vv[2] = c[mi][ni][2] * scale; vv[3] = c[mi][ni][3] * scale;
            if (BIAS) {
                const float b0 = bias[col], b1 = bias[col + 1];
                vv[0] += b0; vv[1] += b1; vv[2] += b0; vv[3] += b1;
            }
            if (SPLIT_OUT) {
                bf16 h[4], l[4];
                #pragma unroll
                for (int e = 0; e < 4; ++e) split_bf(vv[e], h[e], l[e]);
                __nv_bfloat162 t2;
                t2.x = h[0]; t2.y = h[1];
                *reinterpret_cast<__nv_bfloat162*>(Chi + (size_t)r0 * ldc + col) = t2;
                t2.x = h[2]; t2.y = h[3];
                *reinterpret_cast<__nv_bfloat162*>(Chi + (size_t)(r0 + 8) * ldc + col) = t2;
                t2.x = l[0]; t2.y = l[1];
                *reinterpret_cast<__nv_bfloat162*>(Clo + (size_t)r0 * ldc + col) = t2;
                t2.x = l[2]; t2.y = l[3];
                *reinterpret_cast<__nv_bfloat162*>(Clo + (size_t)(r0 + 8) * ldc + col) = t2;
            } else {
                *reinterpret_cast<float2*>(C + (size_t)r0 * ldc + col)       = make_float2(vv[0], vv[1]);
                *reinterpret_cast<float2*>(C + (size_t)(r0 + 8) * ldc + col) = make_float2(vv[2], vv[3]);
            }
        }
    }
}

template<bool BIAS, bool SPLIT_OUT>
__global__ void __launch_bounds__(512, 1)
mma_bf16_kernel(const bf16* __restrict__ Ahi, const bf16* __restrict__ Alo, int lda,
                const bf16* __restrict__ Bhi, const bf16* __restrict__ Blo, int ldb,
                float* __restrict__ C, bf16* __restrict__ Chi, bf16* __restrict__ Clo,
                int ldc, int K, const float* __restrict__ bias, float scale)
{
    extern __shared__ char sm[];
    gemm_body<BIAS, SPLIT_OUT>(Ahi, Alo, lda, Bhi, Blo, ldb, C, Chi, Clo, ldc,
                               K, bias, scale, blockIdx.x, blockIdx.y, sm);
}

// Merged QKV: grid (4, 32, 3)
__global__ void __launch_bounds__(512, 1)
qkv_kernel(const bf16* __restrict__ xhi, const bf16* __restrict__ xlo,
           const bf16* __restrict__ WThi, const bf16* __restrict__ WTlo,
           const float* __restrict__ bq, const float* __restrict__ bk,
           const float* __restrict__ bv,
           bf16* __restrict__ qhi, bf16* __restrict__ qlo,
           float* __restrict__ k, float* __restrict__ v)
{
    extern __shared__ char sm[];
    const int z = blockIdx.z;
    const bf16* Wh = WThi + (size_t)z * DDIM * DDIM;
    const bf16* Wl = WTlo + (size_t)z * DDIM * DDIM;
    if (z == 0)
        gemm_body<true, true>(xhi, xlo, DDIM, Wh, Wl, DDIM, nullptr, qhi, qlo,
                              DDIM, DDIM, bq, 1.0f, blockIdx.x, blockIdx.y, sm);
    else if (z == 1)
        gemm_body<true, false>(xhi, xlo, DDIM, Wh, Wl, DDIM, k, nullptr, nullptr,
                               DDIM, DDIM, bk, 1.0f, blockIdx.x, blockIdx.y, sm);
    else
        gemm_body<true, false>(xhi, xlo, DDIM, Wh, Wl, DDIM, v, nullptr, nullptr,
                               DDIM, DDIM, bv, 1.0f, blockIdx.x, blockIdx.y, sm);
}

// Merged context split-K: grid (4, 32, 4)
__global__ void __launch_bounds__(512, 1)
ctx_kernel(const bf16* __restrict__ atthi, const bf16* __restrict__ attlo,
           const bf16* __restrict__ vThi, const bf16* __restrict__ vTlo,
           float* __restrict__ part)
{
    extern __shared__ char sm[];
    const int z = blockIdx.z;
    gemm_body<false, false>(atthi + z * (N_TOK / 4), attlo + z * (N_TOK / 4), N_TOK,
                            vThi + z * (N_TOK / 4), vTlo + z * (N_TOK / 4), N_TOK,
                            part + (size_t)z * N_TOK * DDIM, nullptr, nullptr, DDIM,
                            N_TOK / 4, nullptr, 1.0f, blockIdx.x, blockIdx.y, sm);
}

// ---------------------------------------------------------------------------
// Elementwise bf16 split
// ---------------------------------------------------------------------------
__global__ void __launch_bounds__(256)
split_kernel(const float* __restrict__ in, bf16* __restrict__ hi, bf16* __restrict__ lo)
{
    const int i = blockIdx.x * blockDim.x + threadIdx.x;
    bf16 h, l;
    split_bf(in[i], h, l);
    hi[i] = h;
    lo[i] = l;
}

// ---------------------------------------------------------------------------
// 32x32 tiled transpose with bf16 split. Merged 3 weights via grid.z.
// ---------------------------------------------------------------------------
__device__ __forceinline__ void transpose_split_body(
    const float* __restrict__ in, bf16* __restrict__ hi, bf16* __restrict__ lo,
    int R, int C)
{
    __shared__ float t[32][33];
    const int bx = blockIdx.x * 32, by = blockIdx.y * 32;
    const int tx = threadIdx.x, ty = threadIdx.y;
    #pragma unroll
    for (int j = 0; j < 32; j += 8)
        t[ty + j][tx] = in[(size_t)(by + ty + j) * C + bx + tx];
    __syncthreads();
    #pragma unroll
    for (int j = 0; j < 32; j += 8) {
        bf16 h, l;
        split_bf(t[tx][ty + j], h, l);
        hi[(size_t)(bx + ty + j) * R + by + tx] = h;
        lo[(size_t)(bx + ty + j) * R + by + tx] = l;
    }
}

__global__ void __launch_bounds__(256)
transpose_split_kernel(const float* __restrict__ in, bf16* __restrict__ hi,
                       bf16* __restrict__ lo, int R, int C)
{
    transpose_split_body(in, hi, lo, R, C);
}

__global__ void __launch_bounds__(256)
wt_transpose_kernel(const float* __restrict__ Wq, const float* __restrict__ Wk,
                    const float* __restrict__ Wv, bf16* __restrict__ hi,
                    bf16* __restrict__ lo)
{
    const int z = blockIdx.z;
    const float* in = (z == 0) ? Wq : (z == 1) ? Wk : Wv;
    transpose_split_body(in, hi + (size_t)z * DDIM * DDIM,
                         lo + (size_t)z * DDIM * DDIM, DDIM, DDIM);
}

// ---------------------------------------------------------------------------
// Exact per-row top-k (4-pass radix select) + masked softmax -> bf16 hi/lo.
// R8: warp-aggregated histogram atomics (__match_any_sync) — pass 0 funnels
// ~4096 values into ~8 exponent bins, which serialized the naive smem atomics
// 32-way. Aggregation makes cost O(values), bin-skew independent. Counts are
// bit-identical, so the threshold (and final output) is bit-identical.
// ---------------------------------------------------------------------------
__global__ void __launch_bounds__(512)
topk_softmax_kernel(const float* __restrict__ score,
                    bf16* __restrict__ atthi, bf16* __restrict__ attlo)
{
    __shared__ uint32_t s[N_TOK];
    __shared__ uint32_t hist[256];
    __shared__ uint32_t sh_sel[2];
    __shared__ float red[16];

    const int tid  = threadIdx.x;
    const int lane = tid & 31;
    const float* row = score + (size_t)blockIdx.x * N_TOK;

    float orig[8];
    uint32_t su[8];
    #pragma unroll
    for (int cidx = 0; cidx < 8; ++cidx) {
        const float f = row[tid + cidx * 512];
        orig[cidx] = f;
        uint32_t u = __float_as_uint(f);
        u ^= (uint32_t)(((int32_t)u) >> 31) | 0x80000000u;
        su[cidx] = u;
        s[tid + cidx * 512] = u;
    }

    uint32_t prefix = 0, rank = KEEP;
    #pragma unroll
    for (int pass = 0; pass < 4; ++pass) {
        const int shift   = 24 - pass * 8;
        const int hishift = (pass == 0) ? 0 : (shift + 8);
        if (tid < 256) hist[tid] = 0;
        __syncthreads();
        #pragma unroll
        for (int cidx = 0; cidx < 8; ++cidx) {
            const uint32_t u = s[tid + cidx * 512];
            const bool match = (pass == 0) || (((u ^ prefix) >> hishift) == 0);
            // warp-aggregated atomic: non-participants get unique dummy bins
            const int bin = match ? (int)((u >> shift) & 0xFFu) : (256 + lane);
            const uint32_t mk = __match_any_sync(0xffffffffu, bin);
            if (match && lane == (__ffs(mk) - 1))
                atomicAdd(&hist[bin], (uint32_t)__popc(mk));
        }
        __syncthreads();
        if (tid < 32) {
            uint32_t h[8], sum = 0;
            #pragma unroll
            for (int i = 0; i < 8; ++i) {
                h[i] = hist[255 - (tid * 8 + i)];
                sum += h[i];
            }
            uint32_t inc = sum;
            #pragma unroll
            for (int o = 1; o < 32; o <<= 1) {
                const uint32_t t = __shfl_up_sync(0xffffffffu, inc, o);
                if (tid >= o) inc += t;
            }
            const uint32_t exc = inc - sum;
            if (exc < rank && rank <= inc) {
                uint32_t cum = exc;
                #pragma unroll
                for (int i = 0; i < 8; ++i) {
                    cum += h[i];
                    if (cum >= rank) {
                        sh_sel[0] = prefix | ((uint32_t)(255 - (tid * 8 + i)) << shift);
                        sh_sel[1] = rank - (cum - h[i]);
                        break;
                    }
                }
            }
        }
        __syncthreads();
        prefix = sh_sel[0];
        rank   = sh_sel[1];
        __syncthreads();
    }
    const uint32_t thr_u = prefix;

    float m[8];
    float lmax = 0.0f;
    #pragma unroll
    for (int cidx = 0; cidx < 8; ++cidx) {
        m[cidx] = (su[cidx] > thr_u) ? orig[cidx] : 0.0f;
        lmax = fmaxf(lmax, m[cidx]);
    }
    #pragma unroll
    for (int o = 16; o; o >>= 1)
        lmax = fmaxf(lmax, __shfl_xor_sync(0xffffffffu, lmax, o));
    if ((tid & 31) == 0) red[tid >> 5] = lmax;
    __syncthreads();
    float gmax;
    {
        float v2 = red[tid & 15];
        #pragma unroll
        for (int o = 8; o; o >>= 1)
            v2 = fmaxf(v2, __shfl_xor_sync(0xffffffffu, v2, o));
        gmax = v2;
    }
    __syncthreads();

    float e[8];
    float lsum = 0.0f;
    #pragma unroll
    for (int cidx = 0; cidx < 8; ++cidx) {
        e[cidx] = expf(m[cidx] - gmax);
        lsum += e[cidx];
    }
    #pragma unroll
    for (int o = 16; o; o >>= 1)
        lsum += __shfl_xor_sync(0xffffffffu, lsum, o);
    if ((tid & 31) == 0) red[tid >> 5] = lsum;
    __syncthreads();
    float gsum;
    {
        float v2 = red[tid & 15];
        #pragma unroll
        for (int o = 8; o; o >>= 1)
            v2 += __shfl_xor_sync(0xffffffffu, v2, o);
        gsum = v2;
    }

    const float inv = 1.0f / gsum;
    #pragma unroll
    for (int cidx = 0; cidx < 8; ++cidx) {
        bf16 h, l;
        split_bf(e[cidx] * inv, h, l);
        atthi[(size_t)blockIdx.x * N_TOK + tid + cidx * 512] = h;
        attlo[(size_t)blockIdx.x * N_TOK + tid + cidx * 512] = l;
    }
}

// ---------------------------------------------------------------------------
// Deterministic 4-way split-K reduce
// ---------------------------------------------------------------------------
__global__ void __launch_bounds__(256)
reduce4_kernel(const float4* __restrict__ p0, const float4* __restrict__ p1,
               const float4* __restrict__ p2, const float4* __restrict__ p3,
               float4* __restrict__ out)
{
    const int i = blockIdx.x * blockDim.x + threadIdx.x;
    float4 a = p0[i], b = p1[i], c = p2[i], d = p3[i];
    float4 o;
    o.x = ((a.x + b.x) + c.x) + d.x;
    o.y = ((a.y + b.y) + c.y) + d.y;
    o.z = ((a.z + b.z) + c.z) + d.z;
    o.w = ((a.w + b.w) + c.w) + d.w;
    out[i] = o;
}

// ---------------------------------------------------------------------------
extern "C" void kernel_launch(void* const* d_in, const int* in_sizes, int n_in,
                              void* d_out, int out_size)
{
    const float* x  = (const float*)d_in[0];
    const float* Wq = (const float*)d_in[1];
    const float* bq = (const float*)d_in[2];
    const float* Wk = (const float*)d_in[3];
    const float* bk = (const float*)d_in[4];
    const float* Wv = (const float*)d_in[5];
    const float* bv = (const float*)d_in[6];
    float* out = (float*)d_out;

    bf16 *xhi, *xlo, *WThi, *WTlo, *qhi, *qlo, *kThi, *kTlo, *vThi, *vTlo, *atthi, *attlo;
    float *k, *v, *score, *part;
    cudaGetSymbolAddress((void**)&xhi,   g_xhi);
    cudaGetSymbolAddress((void**)&xlo,   g_xlo);
    cudaGetSymbolAddress((void**)&WThi,  g_WThi);
    cudaGetSymbolAddress((void**)&WTlo,  g_WTlo);
    cudaGetSymbolAddress((void**)&qhi,   g_qhi);
    cudaGetSymbolAddress((void**)&qlo,   g_qlo);
    cudaGetSymbolAddress((void**)&kThi,  g_kThi);
    cudaGetSymbolAddress((void**)&kTlo,  g_kTlo);
    cudaGetSymbolAddress((void**)&vThi,  g_vThi);
    cudaGetSymbolAddress((void**)&vTlo,  g_vTlo);
    cudaGetSymbolAddress((void**)&atthi, g_atthi);
    cudaGetSymbolAddress((void**)&attlo, g_attlo);
    cudaGetSymbolAddress((void**)&k,     g_k);
    cudaGetSymbolAddress((void**)&v,     g_v);
    cudaGetSymbolAddress((void**)&score, g_score);
    cudaGetSymbolAddress((void**)&part,  g_part);

    cudaFuncSetAttribute(qkv_kernel,
                         cudaFuncAttributeMaxDynamicSharedMemorySize, GEMM_SMEM_BYTES);
    cudaFuncSetAttribute(mma_bf16_kernel<false, false>,
                         cudaFuncAttributeMaxDynamicSharedMemorySize, GEMM_SMEM_BYTES);
    cudaFuncSetAttribute(ctx_kernel,
                         cudaFuncAttributeMaxDynamicSharedMemorySize, GEMM_SMEM_BYTES);

    const float inv_sqrt_d = 1.0f / sqrtf((float)DDIM);
    const dim3 tb(32, 8);

    // Pre-split x; merged weight transpose+split (grid.z = 3)
    split_kernel<<<(N_TOK * DDIM) / 256, 256>>>(x, xhi, xlo);
    wt_transpose_kernel<<<dim3(DDIM / 32, DDIM / 32, 3), tb>>>(Wq, Wk, Wv, WThi, WTlo);

    // QKV merged: grid (4, 32, 3)
    qkv_kernel<<<dim3(DDIM / 128, N_TOK / 128, 3), 512, GEMM_SMEM_BYTES>>>(
        xhi, xlo, WThi, WTlo, bq, bk, bv, qhi, qlo, k, v);

    // kT[n][dd] = (k viewed as [512][4096])^T, split; vT = v^T, split
    transpose_split_kernel<<<dim3(N_TOK / 32, DDIM / 32), tb>>>(k, kThi, kTlo, DDIM, N_TOK);
    transpose_split_kernel<<<dim3(DDIM / 32, N_TOK / 32), tb>>>(v, vThi, vTlo, N_TOK, DDIM);

    // Score: M=N=4096, K=512
    mma_bf16_kernel<false, false><<<dim3(N_TOK / 128, N_TOK / 128), 512, GEMM_SMEM_BYTES>>>(
        qhi, qlo, DDIM, kThi, kTlo, DDIM, score, nullptr, nullptr, N_TOK,
        DDIM, nullptr, inv_sqrt_d);

    // Exact top-k + masked softmax; attn emitted pre-split (bf16)
    topk_softmax_kernel<<<N_TOK, 512>>>(score, atthi, attlo);

    // Context: merged split-K=4, then deterministic reduce
    ctx_kernel<<<dim3(DDIM / 128, N_TOK / 128, 4), 512, GEMM_SMEM_BYTES>>>(
        atthi, attlo, vThi, vTlo, part);
    reduce4_kernel<<<(N_TOK * DDIM / 4) / 256, 256>>>(
        (const float4*)(part + 0 * (size_t)N_TOK * DDIM),
        (const float4*)(part + 1 * (size_t)N_TOK * DDIM),
        (const float4*)(part + 2 * (size_t)N_TOK * DDIM),
        (const float4*)(part + 3 * (size_t)N_TOK * DDIM),
        (float4*)out);
}

// round 9
// speedup vs baseline: 1.6357x; 1.6357x over previous
#include <cuda_runtime.h>
#include <cuda_bf16.h>
#include <cstdint>
#include <math.h>

#define N_TOK 4096
#define DDIM  512
#define KEEP  2048

// ---------------- device scratch (uint4 for 16B alignment) ----------------
__device__ uint4 g_xhi [N_TOK * DDIM / 8];
__device__ uint4 g_xlo [N_TOK * DDIM / 8];
__device__ uint4 g_WThi[3 * DDIM * DDIM / 8];
__device__ uint4 g_WTlo[3 * DDIM * DDIM / 8];
__device__ uint4 g_qhi [N_TOK * DDIM / 8];
__device__ uint4 g_qlo [N_TOK * DDIM / 8];
__device__ uint4 g_kThi[N_TOK * DDIM / 8];
__device__ uint4 g_kTlo[N_TOK * DDIM / 8];
__device__ uint4 g_vThi[N_TOK * DDIM / 8];
__device__ uint4 g_vTlo[N_TOK * DDIM / 8];
__device__ uint4 g_atthi[(size_t)N_TOK * N_TOK / 8];
__device__ uint4 g_attlo[(size_t)N_TOK * N_TOK / 8];
__device__ float g_k[N_TOK * DDIM];
__device__ float g_v[N_TOK * DDIM];
__device__ float g_score[(size_t)N_TOK * N_TOK];
__device__ float g_part[4][N_TOK * DDIM];

typedef __nv_bfloat16 bf16;

// ---------------- helpers ----------------
__device__ __forceinline__ uint32_t smem_u32(const void* p) {
    uint32_t a;
    asm("{ .reg .u64 t; cvta.to.shared.u64 t, %1; cvt.u32.u64 %0, t; }"
        : "=r"(a) : "l"(p));
    return a;
}
__device__ __forceinline__ void split_bf(float f, bf16& h, bf16& l) {
    h = __float2bfloat16_rn(f);
    l = __float2bfloat16_rn(f - __bfloat162float(h));
}

#define CP16(dst, src) \
    asm volatile("cp.async.cg.shared.global [%0], [%1], 16;" :: "r"(dst), "l"(src) : "memory")
#define CP_COMMIT() asm volatile("cp.async.commit_group;" ::: "memory")
#define CP_WAIT1()  asm volatile("cp.async.wait_group 1;" ::: "memory")
#define CP_WAIT0()  asm volatile("cp.async.wait_group 0;" ::: "memory")

#define LDSM4(r, a)                                                             \
    asm volatile("ldmatrix.sync.aligned.m8n8.x4.shared.b16 {%0,%1,%2,%3}, [%4];" \
        : "=r"((r)[0]), "=r"((r)[1]), "=r"((r)[2]), "=r"((r)[3]) : "r"(a))

// m16n8k16 bf16 MMA, D += A*B (row.col), f32 accumulate
#define MMA16(cc, a, b)                                                         \
    asm volatile("mma.sync.aligned.m16n8k16.row.col.f32.bf16.bf16.f32 "         \
        "{%0,%1,%2,%3}, {%4,%5,%6,%7}, {%8,%9}, {%0,%1,%2,%3};"                 \
        : "+f"((cc)[0]), "+f"((cc)[1]), "+f"((cc)[2]), "+f"((cc)[3])            \
        : "r"((a)[0]), "r"((a)[1]), "r"((a)[2]), "r"((a)[3]),                   \
          "r"((b)[0]), "r"((b)[1]))

// ---------------------------------------------------------------------------
// 3xBF16 mma.sync GEMM body: C = scale*(A @ B^T) (+bias)
// ---------------------------------------------------------------------------
#define TILE_B    18432                    // 128 * 144
#define STAGE_ALL (4 * TILE_B)             // 73728
#define GEMM_SMEM_BYTES (2 * STAGE_ALL)    // 147456

template<bool BIAS, bool SPLIT_OUT>
__device__ __forceinline__ void gemm_body(
    const bf16* __restrict__ Ahi, const bf16* __restrict__ Alo, int lda,
    const bf16* __restrict__ Bhi, const bf16* __restrict__ Blo, int ldb,
    float* __restrict__ C, bf16* __restrict__ Chi, bf16* __restrict__ Clo, int ldc,
    int K, const float* __restrict__ bias, float scale,
    int bx, int by, char* sm)
{
    const uint32_t smb = smem_u32(sm);

    const int tid  = threadIdx.x;
    const int w    = tid >> 5;
    const int lane = tid & 31;
    const int wm   = w & 3;
    const int wn   = w >> 2;
    const int g    = lane >> 2;
    const int tig  = lane & 3;

    const int lrow = tid >> 2;
    const int lch  = tid & 3;
    const bf16* pAh = Ahi + (size_t)(by * 128 + lrow) * lda + lch * 16;
    const bf16* pAl = Alo + (size_t)(by * 128 + lrow) * lda + lch * 16;
    const bf16* pBh = Bhi + (size_t)(bx * 128 + lrow) * ldb + lch * 16;
    const bf16* pBl = Blo + (size_t)(bx * 128 + lrow) * ldb + lch * 16;
    const uint32_t so = (uint32_t)lrow * 144 + lch * 32;

    const int l7 = lane & 7;
    const uint32_t aoff0 = (uint32_t)(wm * 32 + ((lane >> 3) & 1) * 8 + l7) * 144
                         + (uint32_t)(lane >> 4) * 16;
    const uint32_t aoff1 = aoff0 + 16u * 144u;
    const uint32_t boff0 = 2u * TILE_B
                         + (uint32_t)(wn * 32 + (lane >> 4) * 8 + l7) * 144
                         + (uint32_t)((lane >> 3) & 1) * 16;
    const uint32_t boff1 = boff0 + 16u * 144u;

    float c[2][4][4] = {};
    const int nT = K >> 6;

    {
        const uint32_t st = smb;
        CP16(st + so,                   pAh);
        CP16(st + so + 16,              pAh + 8);
        CP16(st + TILE_B + so,          pAl);
        CP16(st + TILE_B + so + 16,     pAl + 8);
        CP16(st + 2 * TILE_B + so,      pBh);
        CP16(st + 2 * TILE_B + so + 16, pBh + 8);
        CP16(st + 3 * TILE_B + so,      pBl);
        CP16(st + 3 * TILE_B + so + 16, pBl + 8);
        CP_COMMIT();
    }

    for (int kt = 0; kt < nT; ++kt) {
        if (kt + 1 < nT) {
            const uint32_t st = smb + ((kt + 1) & 1) * STAGE_ALL;
            const int ko = (kt + 1) * 64;
            CP16(st + so,                   pAh + ko);
            CP16(st + so + 16,              pAh + ko + 8);
            CP16(st + TILE_B + so,          pAl + ko);
            CP16(st + TILE_B + so + 16,     pAl + ko + 8);
            CP16(st + 2 * TILE_B + so,      pBh + ko);
            CP16(st + 2 * TILE_B + so + 16, pBh + ko + 8);
            CP16(st + 3 * TILE_B + so,      pBl + ko);
            CP16(st + 3 * TILE_B + so + 16, pBl + ko + 8);
            CP_COMMIT();
            CP_WAIT1();
        } else {
            CP_WAIT0();
        }
        __syncthreads();

        const uint32_t stb = smb + (kt & 1) * STAGE_ALL;

        #pragma unroll
        for (int ks = 0; ks < 4; ++ks) {
            const uint32_t koff = (uint32_t)ks * 32;

            uint32_t ah[2][4], al[2][4], bh[2][4], bl[2][4];
            LDSM4(ah[0], stb + aoff0 + koff);
            LDSM4(ah[1], stb + aoff1 + koff);
            LDSM4(bh[0], stb + boff0 + koff);
            LDSM4(bh[1], stb + boff1 + koff);
            LDSM4(al[0], stb + TILE_B + aoff0 + koff);
            LDSM4(al[1], stb + TILE_B + aoff1 + koff);
            LDSM4(bl[0], stb + TILE_B + boff0 + koff);
            LDSM4(bl[1], stb + TILE_B + boff1 + koff);

            #pragma unroll
            for (int mi = 0; mi < 2; ++mi)
                #pragma unroll
                for (int ni = 0; ni < 4; ++ni)
                    MMA16(c[mi][ni], ah[mi], bh[ni >> 1] + (ni & 1) * 2);
            #pragma unroll
            for (int mi = 0; mi < 2; ++mi)
                #pragma unroll
                for (int ni = 0; ni < 4; ++ni)
                    MMA16(c[mi][ni], al[mi], bh[ni >> 1] + (ni & 1) * 2);
            #pragma unroll
            for (int mi = 0; mi < 2; ++mi)
                #pragma unroll
                for (int ni = 0; ni < 4; ++ni)
                    MMA16(c[mi][ni], ah[mi], bl[ni >> 1] + (ni & 1) * 2);
        }
        __syncthreads();
    }

    #pragma unroll
    for (int mi = 0; mi < 2; ++mi) {
        const int r0 = by * 128 + wm * 32 + mi * 16 + g;
        #pragma unroll
        for (int ni = 0; ni < 4; ++ni) {
            const int col = bx * 128 + wn * 32 + ni * 8 + tig * 2;
            float vv[4];
            vv[0] = c[mi][ni][0] * scale; vv[1] = c[mi][ni][1] * scale;
            vv[2] = c[mi][ni][2] * scale; vv[3] = c[mi][ni][3] * scale;
            if (BIAS) {
                const float b0 = bias[col], b1 = bias[col + 1];
                vv[0] += b0; vv[1] += b1; vv[2] += b0; vv[3] += b1;
            }
            if (SPLIT_OUT) {
                bf16 h[4], l[4];
                #pragma unroll
                for (int e = 0; e < 4; ++e) split_bf(vv[e], h[e], l[e]);
                __nv_bfloat162 t2;
                t2.x = h[0]; t2.y = h[1];
                *reinterpret_cast<__nv_bfloat162*>(Chi + (size_t)r0 * ldc + col) = t2;
                t2.x = h[2]; t2.y = h[3];
                *reinterpret_cast<__nv_bfloat162*>(Chi + (size_t)(r0 + 8) * ldc + col) = t2;
                t2.x = l[0]; t2.y = l[1];
                *reinterpret_cast<__nv_bfloat162*>(Clo + (size_t)r0 * ldc + col) = t2;
                t2.x = l[2]; t2.y = l[3];
                *reinterpret_cast<__nv_bfloat162*>(Clo + (size_t)(r0 + 8) * ldc + col) = t2;
            } else {
                *reinterpret_cast<float2*>(C + (size_t)r0 * ldc + col)       = make_float2(vv[0], vv[1]);
                *reinterpret_cast<float2*>(C + (size_t)(r0 + 8) * ldc + col) = make_float2(vv[2], vv[3]);
            }
        }
    }
}

template<bool BIAS, bool SPLIT_OUT>
__global__ void __launch_bounds__(512, 1)
mma_bf16_kernel(const bf16* __restrict__ Ahi, const bf16* __restrict__ Alo, int lda,
                const bf16* __restrict__ Bhi, const bf16* __restrict__ Blo, int ldb,
                float* __restrict__ C, bf16* __restrict__ Chi, bf16* __restrict__ Clo,
                int ldc, int K, const float* __restrict__ bias, float scale)
{
    extern __shared__ char sm[];
    gemm_body<BIAS, SPLIT_OUT>(Ahi, Alo, lda, Bhi, Blo, ldb, C, Chi, Clo, ldc,
                               K, bias, scale, blockIdx.x, blockIdx.y, sm);
}

// Merged QKV: grid (4, 32, 3)
__global__ void __launch_bounds__(512, 1)
qkv_kernel(const bf16* __restrict__ xhi, const bf16* __restrict__ xlo,
           const bf16* __restrict__ WThi, const bf16* __restrict__ WTlo,
           const float* __restrict__ bq, const float* __restrict__ bk,
           const float* __restrict__ bv,
           bf16* __restrict__ qhi, bf16* __restrict__ qlo,
           float* __restrict__ k, float* __restrict__ v)
{
    extern __shared__ char sm[];
    const int z = blockIdx.z;
    const bf16* Wh = WThi + (size_t)z * DDIM * DDIM;
    const bf16* Wl = WTlo + (size_t)z * DDIM * DDIM;
    if (z == 0)
        gemm_body<true, true>(xhi, xlo, DDIM, Wh, Wl, DDIM, nullptr, qhi, qlo,
                              DDIM, DDIM, bq, 1.0f, blockIdx.x, blockIdx.y, sm);
    else if (z == 1)
        gemm_body<true, false>(xhi, xlo, DDIM, Wh, Wl, DDIM, k, nullptr, nullptr,
                               DDIM, DDIM, bk, 1.0f, blockIdx.x, blockIdx.y, sm);
    else
        gemm_body<true, false>(xhi, xlo, DDIM, Wh, Wl, DDIM, v, nullptr, nullptr,
                               DDIM, DDIM, bv, 1.0f, blockIdx.x, blockIdx.y, sm);
}

// Merged context split-K: grid (4, 32, 4)
__global__ void __launch_bounds__(512, 1)
ctx_kernel(const bf16* __restrict__ atthi, const bf16* __restrict__ attlo,
           const bf16* __restrict__ vThi, const bf16* __restrict__ vTlo,
           float* __restrict__ part)
{
    extern __shared__ char sm[];
    const int z = blockIdx.z;
    gemm_body<false, false>(atthi + z * (N_TOK / 4), attlo + z * (N_TOK / 4), N_TOK,
                            vThi + z * (N_TOK / 4), vTlo + z * (N_TOK / 4), N_TOK,
                            part + (size_t)z * N_TOK * DDIM, nullptr, nullptr, DDIM,
                            N_TOK / 4, nullptr, 1.0f, blockIdx.x, blockIdx.y, sm);
}

// ---------------------------------------------------------------------------
// Elementwise bf16 split
// ---------------------------------------------------------------------------
__global__ void __launch_bounds__(256)
split_kernel(const float* __restrict__ in, bf16* __restrict__ hi, bf16* __restrict__ lo)
{
    const int i = blockIdx.x * blockDim.x + threadIdx.x;
    bf16 h, l;
    split_bf(in[i], h, l);
    hi[i] = h;
    lo[i] = l;
}

// ---------------------------------------------------------------------------
// 32x32 tiled transpose with bf16 split. Merged 3 weights via grid.z.
// ---------------------------------------------------------------------------
__device__ __forceinline__ void transpose_split_body(
    const float* __restrict__ in, bf16* __restrict__ hi, bf16* __restrict__ lo,
    int R, int C)
{
    __shared__ float t[32][33];
    const int bx = blockIdx.x * 32, by = blockIdx.y * 32;
    const int tx = threadIdx.x, ty = threadIdx.y;
    #pragma unroll
    for (int j = 0; j < 32; j += 8)
        t[ty + j][tx] = in[(size_t)(by + ty + j) * C + bx + tx];
    __syncthreads();
    #pragma unroll
    for (int j = 0; j < 32; j += 8) {
        bf16 h, l;
        split_bf(t[tx][ty + j], h, l);
        hi[(size_t)(bx + ty + j) * R + by + tx] = h;
        lo[(size_t)(bx + ty + j) * R + by + tx] = l;
    }
}

__global__ void __launch_bounds__(256)
transpose_split_kernel(const float* __restrict__ in, bf16* __restrict__ hi,
                       bf16* __restrict__ lo, int R, int C)
{
    transpose_split_body(in, hi, lo, R, C);
}

__global__ void __launch_bounds__(256)
wt_transpose_kernel(const float* __restrict__ Wq, const float* __restrict__ Wk,
                    const float* __restrict__ Wv, bf16* __restrict__ hi,
                    bf16* __restrict__ lo)
{
    const int z = blockIdx.z;
    const float* in = (z == 0) ? Wq : (z == 1) ? Wk : Wv;
    transpose_split_body(in, hi + (size_t)z * DDIM * DDIM,
                         lo + (size_t)z * DDIM * DDIM, DDIM, DDIM);
}

// ---------------------------------------------------------------------------
// Exact per-row top-k (4-pass radix select) + masked softmax -> bf16 hi/lo.
// R9: plain smem atomics (R8's MATCH.ANY aggregation cost ~300us — reverted),
// with 4 privatized histogram copies (one per 4-warp group) to cut inter-warp
// same-bin collisions in the skewed pass 0. Counts bit-identical.
// ---------------------------------------------------------------------------
__global__ void __launch_bounds__(512)
topk_softmax_kernel(const float* __restrict__ score,
                    bf16* __restrict__ atthi, bf16* __restrict__ attlo)
{
    __shared__ uint32_t s[N_TOK];
    __shared__ uint32_t hist[4][256];
    __shared__ uint32_t sh_sel[2];
    __shared__ float red[16];

    const int tid = threadIdx.x;
    const int hc  = (tid >> 7) & 3;     // histogram copy = warp group
    const float* row = score + (size_t)blockIdx.x * N_TOK;

    float orig[8];
    uint32_t su[8];
    #pragma unroll
    for (int cidx = 0; cidx < 8; ++cidx) {
        const float f = row[tid + cidx * 512];
        orig[cidx] = f;
        uint32_t u = __float_as_uint(f);
        u ^= (uint32_t)(((int32_t)u) >> 31) | 0x80000000u;
        su[cidx] = u;
        s[tid + cidx * 512] = u;
    }

    uint32_t prefix = 0, rank = KEEP;
    #pragma unroll
    for (int pass = 0; pass < 4; ++pass) {
        const int shift   = 24 - pass * 8;
        const int hishift = (pass == 0) ? 0 : (shift + 8);
        if (tid < 256) {
            hist[0][tid] = 0; hist[1][tid] = 0;
            hist[2][tid] = 0; hist[3][tid] = 0;
        }
        __syncthreads();
        #pragma unroll
        for (int cidx = 0; cidx < 8; ++cidx) {
            const uint32_t u = s[tid + cidx * 512];
            const bool match = (pass == 0) || (((u ^ prefix) >> hishift) == 0);
            if (match) atomicAdd(&hist[hc][(u >> shift) & 0xFFu], 1u);
        }
        __syncthreads();
        if (tid < 32) {
            uint32_t h[8], sum = 0;
            #pragma unroll
            for (int i = 0; i < 8; ++i) {
                const int b = 255 - (tid * 8 + i);
                h[i] = hist[0][b] + hist[1][b] + hist[2][b] + hist[3][b];
                sum += h[i];
            }
            uint32_t inc = sum;
            #pragma unroll
            for (int o = 1; o < 32; o <<= 1) {
                const uint32_t t = __shfl_up_sync(0xffffffffu, inc, o);
                if (tid >= o) inc += t;
            }
            const uint32_t exc = inc - sum;
            if (exc < rank && rank <= inc) {
                uint32_t cum = exc;
                #pragma unroll
                for (int i = 0; i < 8; ++i) {
                    cum += h[i];
                    if (cum >= rank) {
                        sh_sel[0] = prefix | ((uint32_t)(255 - (tid * 8 + i)) << shift);
                        sh_sel[1] = rank - (cum - h[i]);
                        break;
                    }
                }
            }
        }
        __syncthreads();
        prefix = sh_sel[0];
        rank   = sh_sel[1];
        __syncthreads();
    }
    const uint32_t thr_u = prefix;

    float m[8];
    float lmax = 0.0f;
    #pragma unroll
    for (int cidx = 0; cidx < 8; ++cidx) {
        m[cidx] = (su[cidx] > thr_u) ? orig[cidx] : 0.0f;
        lmax = fmaxf(lmax, m[cidx]);
    }
    #pragma unroll
    for (int o = 16; o; o >>= 1)
        lmax = fmaxf(lmax, __shfl_xor_sync(0xffffffffu, lmax, o));
    if ((tid & 31) == 0) red[tid >> 5] = lmax;
    __syncthreads();
    float gmax;
    {
        float v2 = red[tid & 15];
        #pragma unroll
        for (int o = 8; o; o >>= 1)
            v2 = fmaxf(v2, __shfl_xor_sync(0xffffffffu, v2, o));
        gmax = v2;
    }
    __syncthreads();

    float e[8];
    float lsum = 0.0f;
    #pragma unroll
    for (int cidx = 0; cidx < 8; ++cidx) {
        e[cidx] = expf(m[cidx] - gmax);
        lsum += e[cidx];
    }
    #pragma unroll
    for (int o = 16; o; o >>= 1)
        lsum += __shfl_xor_sync(0xffffffffu, lsum, o);
    if ((tid & 31) == 0) red[tid >> 5] = lsum;
    __syncthreads();
    float gsum;
    {
        float v2 = red[tid & 15];
        #pragma unroll
        for (int o = 8; o; o >>= 1)
            v2 += __shfl_xor_sync(0xffffffffu, v2, o);
        gsum = v2;
    }

    const float inv = 1.0f / gsum;
    #pragma unroll
    for (int cidx = 0; cidx < 8; ++cidx) {
        bf16 h, l;
        split_bf(e[cidx] * inv, h, l);
        atthi[(size_t)blockIdx.x * N_TOK + tid + cidx * 512] = h;
        attlo[(size_t)blockIdx.x * N_TOK + tid + cidx * 512] = l;
    }
}

// ---------------------------------------------------------------------------
// Deterministic 4-way split-K reduce
// ---------------------------------------------------------------------------
__global__ void __launch_bounds__(256)
reduce4_kernel(const float4* __restrict__ p0, const float4* __restrict__ p1,
               const float4* __restrict__ p2, const float4* __restrict__ p3,
               float4* __restrict__ out)
{
    const int i = blockIdx.x * blockDim.x + threadIdx.x;
    float4 a = p0[i], b = p1[i], c = p2[i], d = p3[i];
    float4 o;
    o.x = ((a.x + b.x) + c.x) + d.x;
    o.y = ((a.y + b.y) + c.y) + d.y;
    o.z = ((a.z + b.z) + c.z) + d.z;
    o.w = ((a.w + b.w) + c.w) + d.w;
    out[i] = o;
}

// ---------------------------------------------------------------------------
extern "C" void kernel_launch(void* const* d_in, const int* in_sizes, int n_in,
                              void* d_out, int out_size)
{
    const float* x  = (const float*)d_in[0];
    const float* Wq = (const float*)d_in[1];
    const float* bq = (const float*)d_in[2];
    const float* Wk = (const float*)d_in[3];
    const float* bk = (const float*)d_in[4];
    const float* Wv = (const float*)d_in[5];
    const float* bv = (const float*)d_in[6];
    float* out = (float*)d_out;

    bf16 *xhi, *xlo, *WThi, *WTlo, *qhi, *qlo, *kThi, *kTlo, *vThi, *vTlo, *atthi, *attlo;
    float *k, *v, *score, *part;
    cudaGetSymbolAddress((void**)&xhi,   g_xhi);
    cudaGetSymbolAddress((void**)&xlo,   g_xlo);
    cudaGetSymbolAddress((void**)&WThi,  g_WThi);
    cudaGetSymbolAddress((void**)&WTlo,  g_WTlo);
    cudaGetSymbolAddress((void**)&qhi,   g_qhi);
    cudaGetSymbolAddress((void**)&qlo,   g_qlo);
    cudaGetSymbolAddress((void**)&kThi,  g_kThi);
    cudaGetSymbolAddress((void**)&kTlo,  g_kTlo);
    cudaGetSymbolAddress((void**)&vThi,  g_vThi);
    cudaGetSymbolAddress((void**)&vTlo,  g_vTlo);
    cudaGetSymbolAddress((void**)&atthi, g_atthi);
    cudaGetSymbolAddress((void**)&attlo, g_attlo);
    cudaGetSymbolAddress((void**)&k,     g_k);
    cudaGetSymbolAddress((void**)&v,     g_v);
    cudaGetSymbolAddress((void**)&score, g_score);
    cudaGetSymbolAddress((void**)&part,  g_part);

    cudaFuncSetAttribute(qkv_kernel,
                         cudaFuncAttributeMaxDynamicSharedMemorySize, GEMM_SMEM_BYTES);
    cudaFuncSetAttribute(mma_bf16_kernel<false, false>,
                         cudaFuncAttributeMaxDynamicSharedMemorySize, GEMM_SMEM_BYTES);
    cudaFuncSetAttribute(ctx_kernel,
                         cudaFuncAttributeMaxDynamicSharedMemorySize, GEMM_SMEM_BYTES);

    const float inv_sqrt_d = 1.0f / sqrtf((float)DDIM);
    const dim3 tb(32, 8);

    // Pre-split x; merged weight transpose+split (grid.z = 3)
    split_kernel<<<(N_TOK * DDIM) / 256, 256>>>(x, xhi, xlo);
    wt_transpose_kernel<<<dim3(DDIM / 32, DDIM / 32, 3), tb>>>(Wq, Wk, Wv, WThi, WTlo);

    // QKV merged: grid (4, 32, 3)
    qkv_kernel<<<dim3(DDIM / 128, N_TOK / 128, 3), 512, GEMM_SMEM_BYTES>>>(
        xhi, xlo, WThi, WTlo, bq, bk, bv, qhi, qlo, k, v);

    // kT[n][dd] = (k viewed as [512][4096])^T, split; vT = v^T, split
    transpose_split_kernel<<<dim3(N_TOK / 32, DDIM / 32), tb>>>(k, kThi, kTlo, DDIM, N_TOK);
    transpose_split_kernel<<<dim3(DDIM / 32, N_TOK / 32), tb>>>(v, vThi, vTlo, N_TOK, DDIM);

    // Score: M=N=4096, K=512
    mma_bf16_kernel<false, false><<<dim3(N_TOK / 128, N_TOK / 128), 512, GEMM_SMEM_BYTES>>>(
        qhi, qlo, DDIM, kThi, kTlo, DDIM, score, nullptr, nullptr, N_TOK,
        DDIM, nullptr, inv_sqrt_d);

    // Exact top-k + masked softmax; attn emitted pre-split (bf16)
    topk_softmax_kernel<<<N_TOK, 512>>>(score, atthi, attlo);

    // Context: merged split-K=4, then deterministic reduce
    ctx_kernel<<<dim3(DDIM / 128, N_TOK / 128, 4), 512, GEMM_SMEM_BYTES>>>(
        atthi, attlo, vThi, vTlo, part);
    reduce4_kernel<<<(N_TOK * DDIM / 4) / 256, 256>>>(
        (const float4*)(part + 0 * (size_t)N_TOK * DDIM),
        (const float4*)(part + 1 * (size_t)N_TOK * DDIM),
        (const float4*)(part + 2 * (size_t)N_TOK * DDIM),
        (const float4*)(part + 3 * (size_t)N_TOK * DDIM),
        (float4*)out);
}

// round 10
// speedup vs baseline: 2.1849x; 1.3357x over previous
#include <cuda_runtime.h>
#include <cuda_fp16.h>
#include <cstdint>
#include <math.h>

#define N_TOK 4096
#define DDIM  512
#define KEEP  2048

// ---------------- device scratch (uint4 for 16B alignment) ----------------
__device__ uint4 g_xhi [N_TOK * DDIM / 8];
__device__ uint4 g_xlo [N_TOK * DDIM / 8];
__device__ uint4 g_WThi[3 * DDIM * DDIM / 8];
__device__ uint4 g_qhi [N_TOK * DDIM / 8];
__device__ uint4 g_qlo [N_TOK * DDIM / 8];
__device__ uint4 g_kThi[N_TOK * DDIM / 8];
__device__ uint4 g_vThi[N_TOK * DDIM / 8];
__device__ uint4 g_atthi[(size_t)N_TOK * N_TOK / 8];
__device__ uint4 g_attlo[(size_t)N_TOK * N_TOK / 8];
__device__ float g_k[N_TOK * DDIM];
__device__ float g_v[N_TOK * DDIM];
__device__ float g_score[(size_t)N_TOK * N_TOK];
__device__ float g_part[8][N_TOK * DDIM];

typedef __half fp16;

// ---------------- helpers ----------------
__device__ __forceinline__ uint32_t smem_u32(const void* p) {
    uint32_t a;
    asm("{ .reg .u64 t; cvta.to.shared.u64 t, %1; cvt.u32.u64 %0, t; }"
        : "=r"(a) : "l"(p));
    return a;
}
__device__ __forceinline__ void split_hf(float f, fp16& h, fp16& l) {
    h = __float2half_rn(f);
    l = __float2half_rn(f - __half2float(h));
}

#define CP16(dst, src) \
    asm volatile("cp.async.cg.shared.global [%0], [%1], 16;" :: "r"(dst), "l"(src) : "memory")
#define CP_COMMIT() asm volatile("cp.async.commit_group;" ::: "memory")
#define CP_WAIT1()  asm volatile("cp.async.wait_group 1;" ::: "memory")
#define CP_WAIT0()  asm volatile("cp.async.wait_group 0;" ::: "memory")

#define LDSM4(r, a)                                                             \
    asm volatile("ldmatrix.sync.aligned.m8n8.x4.shared.b16 {%0,%1,%2,%3}, [%4];" \
        : "=r"((r)[0]), "=r"((r)[1]), "=r"((r)[2]), "=r"((r)[3]) : "r"(a))

// m16n8k16 fp16 MMA, D += A*B (row.col), f32 accumulate
#define MMA16(cc, a, b)                                                         \
    asm volatile("mma.sync.aligned.m16n8k16.row.col.f32.f16.f16.f32 "           \
        "{%0,%1,%2,%3}, {%4,%5,%6,%7}, {%8,%9}, {%0,%1,%2,%3};"                 \
        : "+f"((cc)[0]), "+f"((cc)[1]), "+f"((cc)[2]), "+f"((cc)[3])            \
        : "r"((a)[0]), "r"((a)[1]), "r"((a)[2]), "r"((a)[3]),                   \
          "r"((b)[0]), "r"((b)[1]))

// ---------------------------------------------------------------------------
// 2-product fp16 GEMM body: C = scale*((Ahi+Alo) @ Bhi^T) (+bias)
// Ahi/Alo [M,K], Bhi [N,K] fp16 row-major. Block 128x128, BK=64,
// 512 threads / 16 warps 4x4, warp tile 32x32. Smem: 2 stages x 3 tiles of
// 128 rows x 144B pitch = 110592 B total.
// ---------------------------------------------------------------------------
#define TILE_B    18432                    // 128 * 144
#define STAGE_ALL (3 * TILE_B)             // 55296
#define GEMM_SMEM_BYTES (2 * STAGE_ALL)    // 110592

template<bool BIAS, bool SPLIT_OUT>
__device__ __forceinline__ void gemm_body(
    const fp16* __restrict__ Ahi, const fp16* __restrict__ Alo, int lda,
    const fp16* __restrict__ Bhi, int ldb,
    float* __restrict__ C, fp16* __restrict__ Chi, fp16* __restrict__ Clo, int ldc,
    int K, const float* __restrict__ bias, float scale,
    int bx, int by, char* sm)
{
    const uint32_t smb = smem_u32(sm);

    const int tid  = threadIdx.x;
    const int w    = tid >> 5;
    const int lane = tid & 31;
    const int wm   = w & 3;
    const int wn   = w >> 2;
    const int g    = lane >> 2;
    const int tig  = lane & 3;

    const int lrow = tid >> 2;
    const int lch  = tid & 3;
    const fp16* pAh = Ahi + (size_t)(by * 128 + lrow) * lda + lch * 16;
    const fp16* pAl = Alo + (size_t)(by * 128 + lrow) * lda + lch * 16;
    const fp16* pBh = Bhi + (size_t)(bx * 128 + lrow) * ldb + lch * 16;
    const uint32_t so = (uint32_t)lrow * 144 + lch * 32;

    const int l7 = lane & 7;
    const uint32_t aoff0 = (uint32_t)(wm * 32 + ((lane >> 3) & 1) * 8 + l7) * 144
                         + (uint32_t)(lane >> 4) * 16;
    const uint32_t aoff1 = aoff0 + 16u * 144u;
    const uint32_t boff0 = 2u * TILE_B
                         + (uint32_t)(wn * 32 + (lane >> 4) * 8 + l7) * 144
                         + (uint32_t)((lane >> 3) & 1) * 16;
    const uint32_t boff1 = boff0 + 16u * 144u;

    float c[2][4][4] = {};
    const int nT = K >> 6;

    {
        const uint32_t st = smb;
        CP16(st + so,                   pAh);
        CP16(st + so + 16,              pAh + 8);
        CP16(st + TILE_B + so,          pAl);
        CP16(st + TILE_B + so + 16,     pAl + 8);
        CP16(st + 2 * TILE_B + so,      pBh);
        CP16(st + 2 * TILE_B + so + 16, pBh + 8);
        CP_COMMIT();
    }

    for (int kt = 0; kt < nT; ++kt) {
        if (kt + 1 < nT) {
            const uint32_t st = smb + ((kt + 1) & 1) * STAGE_ALL;
            const int ko = (kt + 1) * 64;
            CP16(st + so,                   pAh + ko);
            CP16(st + so + 16,              pAh + ko + 8);
            CP16(st + TILE_B + so,          pAl + ko);
            CP16(st + TILE_B + so + 16,     pAl + ko + 8);
            CP16(st + 2 * TILE_B + so,      pBh + ko);
            CP16(st + 2 * TILE_B + so + 16, pBh + ko + 8);
            CP_COMMIT();
            CP_WAIT1();
        } else {
            CP_WAIT0();
        }
        __syncthreads();

        const uint32_t stb = smb + (kt & 1) * STAGE_ALL;

        #pragma unroll
        for (int ks = 0; ks < 4; ++ks) {
            const uint32_t koff = (uint32_t)ks * 32;

            uint32_t ah[2][4], al[2][4], bh[2][4];
            LDSM4(ah[0], stb + aoff0 + koff);
            LDSM4(ah[1], stb + aoff1 + koff);
            LDSM4(bh[0], stb + boff0 + koff);
            LDSM4(bh[1], stb + boff1 + koff);
            LDSM4(al[0], stb + TILE_B + aoff0 + koff);
            LDSM4(al[1], stb + TILE_B + aoff1 + koff);

            #pragma unroll
            for (int mi = 0; mi < 2; ++mi)
                #pragma unroll
                for (int ni = 0; ni < 4; ++ni)
                    MMA16(c[mi][ni], ah[mi], bh[ni >> 1] + (ni & 1) * 2);
            #pragma unroll
            for (int mi = 0; mi < 2; ++mi)
                #pragma unroll
                for (int ni = 0; ni < 4; ++ni)
                    MMA16(c[mi][ni], al[mi], bh[ni >> 1] + (ni & 1) * 2);
        }
        __syncthreads();
    }

    #pragma unroll
    for (int mi = 0; mi < 2; ++mi) {
        const int r0 = by * 128 + wm * 32 + mi * 16 + g;
        #pragma unroll
        for (int ni = 0; ni < 4; ++ni) {
            const int col = bx * 128 + wn * 32 + ni * 8 + tig * 2;
            float vv[4];
            vv[0] = c[mi][ni][0] * scale; vv[1] = c[mi][ni][1] * scale;
            vv[2] = c[mi][ni][2] * scale; vv[3] = c[mi][ni][3] * scale;
            if (BIAS) {
                const float b0 = bias[col], b1 = bias[col + 1];
                vv[0] += b0; vv[1] += b1; vv[2] += b0; vv[3] += b1;
            }
            if (SPLIT_OUT) {
                fp16 h[4], l[4];
                #pragma unroll
                for (int e = 0; e < 4; ++e) split_hf(vv[e], h[e], l[e]);
                __half2 t2;
                t2.x = h[0]; t2.y = h[1];
                *reinterpret_cast<__half2*>(Chi + (size_t)r0 * ldc + col) = t2;
                t2.x = h[2]; t2.y = h[3];
                *reinterpret_cast<__half2*>(Chi + (size_t)(r0 + 8) * ldc + col) = t2;
                t2.x = l[0]; t2.y = l[1];
                *reinterpret_cast<__half2*>(Clo + (size_t)r0 * ldc + col) = t2;
                t2.x = l[2]; t2.y = l[3];
                *reinterpret_cast<__half2*>(Clo + (size_t)(r0 + 8) * ldc + col) = t2;
            } else {
                *reinterpret_cast<float2*>(C + (size_t)r0 * ldc + col)       = make_float2(vv[0], vv[1]);
                *reinterpret_cast<float2*>(C + (size_t)(r0 + 8) * ldc + col) = make_float2(vv[2], vv[3]);
            }
        }
    }
}

template<bool BIAS, bool SPLIT_OUT>
__global__ void __launch_bounds__(512, 1)
mma_hf_kernel(const fp16* __restrict__ Ahi, const fp16* __restrict__ Alo, int lda,
              const fp16* __restrict__ Bhi, int ldb,
              float* __restrict__ C, fp16* __restrict__ Chi, fp16* __restrict__ Clo,
              int ldc, int K, const float* __restrict__ bias, float scale)
{
    extern __shared__ char sm[];
    gemm_body<BIAS, SPLIT_OUT>(Ahi, Alo, lda, Bhi, ldb, C, Chi, Clo, ldc,
                               K, bias, scale, blockIdx.x, blockIdx.y, sm);
}

// Merged QKV: grid (4, 32, 3)
__global__ void __launch_bounds__(512, 1)
qkv_kernel(const fp16* __restrict__ xhi, const fp16* __restrict__ xlo,
           const fp16* __restrict__ WThi,
           const float* __restrict__ bq, const float* __restrict__ bk,
           const float* __restrict__ bv,
           fp16* __restrict__ qhi, fp16* __restrict__ qlo,
           float* __restrict__ k, float* __restrict__ v)
{
    extern __shared__ char sm[];
    const int z = blockIdx.z;
    const fp16* Wh = WThi + (size_t)z * DDIM * DDIM;
    if (z == 0)
        gemm_body<true, true>(xhi, xlo, DDIM, Wh, DDIM, nullptr, qhi, qlo,
                              DDIM, DDIM, bq, 1.0f, blockIdx.x, blockIdx.y, sm);
    else if (z == 1)
        gemm_body<true, false>(xhi, xlo, DDIM, Wh, DDIM, k, nullptr, nullptr,
                               DDIM, DDIM, bk, 1.0f, blockIdx.x, blockIdx.y, sm);
    else
        gemm_body<true, false>(xhi, xlo, DDIM, Wh, DDIM, v, nullptr, nullptr,
                               DDIM, DDIM, bv, 1.0f, blockIdx.x, blockIdx.y, sm);
}

// Merged context split-K=8: grid (4, 32, 8)
__global__ void __launch_bounds__(512, 1)
ctx_kernel(const fp16* __restrict__ atthi, const fp16* __restrict__ attlo,
           const fp16* __restrict__ vThi, float* __restrict__ part)
{
    extern __shared__ char sm[];
    const int z = blockIdx.z;
    gemm_body<false, false>(atthi + z * (N_TOK / 8), attlo + z * (N_TOK / 8), N_TOK,
                            vThi + z * (N_TOK / 8), N_TOK,
                            part + (size_t)z * N_TOK * DDIM, nullptr, nullptr, DDIM,
                            N_TOK / 8, nullptr, 1.0f, blockIdx.x, blockIdx.y, sm);
}

// ---------------------------------------------------------------------------
// Elementwise fp16 split (x -> hi, lo)
// ---------------------------------------------------------------------------
__global__ void __launch_bounds__(256)
split_kernel(const float* __restrict__ in, fp16* __restrict__ hi, fp16* __restrict__ lo)
{
    const int i = blockIdx.x * blockDim.x + threadIdx.x;
    fp16 h, l;
    split_hf(in[i], h, l);
    hi[i] = h;
    lo[i] = l;
}

// ---------------------------------------------------------------------------
// 32x32 tiled transpose, fp16 hi-only output (B operands drop lo).
// ---------------------------------------------------------------------------
__device__ __forceinline__ void transpose_hi_body(
    const float* __restrict__ in, fp16* __restrict__ hi, int R, int C)
{
    __shared__ float t[32][33];
    const int bx = blockIdx.x * 32, by = blockIdx.y * 32;
    const int tx = threadIdx.x, ty = threadIdx.y;
    #pragma unroll
    for (int j = 0; j < 32; j += 8)
        t[ty + j][tx] = in[(size_t)(by + ty + j) * C + bx + tx];
    __syncthreads();
    #pragma unroll
    for (int j = 0; j < 32; j += 8)
        hi[(size_t)(bx + ty + j) * R + by + tx] = __float2half_rn(t[tx][ty + j]);
}

__global__ void __launch_bounds__(256)
transpose_hi_kernel(const float* __restrict__ in, fp16* __restrict__ hi, int R, int C)
{
    transpose_hi_body(in, hi, R, C);
}

__global__ void __launch_bounds__(256)
wt_transpose_kernel(const float* __restrict__ Wq, const float* __restrict__ Wk,
                    const float* __restrict__ Wv, fp16* __restrict__ hi)
{
    const int z = blockIdx.z;
    const float* in = (z == 0) ? Wq : (z == 1) ? Wk : Wv;
    transpose_hi_body(in, hi + (size_t)z * DDIM * DDIM, DDIM, DDIM);
}

// ---------------------------------------------------------------------------
// Exact per-row top-k (4-pass radix select, plain smem atomics — R7 form) +
// masked softmax; emits attn pre-split to fp16 hi/lo. One block (512 thr)/row.
// ---------------------------------------------------------------------------
__global__ void __launch_bounds__(512)
topk_softmax_kernel(const float* __restrict__ score,
                    fp16* __restrict__ atthi, fp16* __restrict__ attlo)
{
    __shared__ uint32_t s[N_TOK];
    __shared__ uint32_t hist[256];
    __shared__ uint32_t sh_sel[2];
    __shared__ float red[16];

    const int tid = threadIdx.x;
    const float* row = score + (size_t)blockIdx.x * N_TOK;

    float orig[8];
    uint32_t su[8];
    #pragma unroll
    for (int cidx = 0; cidx < 8; ++cidx) {
        const float f = row[tid + cidx * 512];
        orig[cidx] = f;
        uint32_t u = __float_as_uint(f);
        u ^= (uint32_t)(((int32_t)u) >> 31) | 0x80000000u;
        su[cidx] = u;
        s[tid + cidx * 512] = u;
    }

    uint32_t prefix = 0, rank = KEEP;
    #pragma unroll
    for (int pass = 0; pass < 4; ++pass) {
        const int shift   = 24 - pass * 8;
        const int hishift = (pass == 0) ? 0 : (shift + 8);
        if (tid < 256) hist[tid] = 0;
        __syncthreads();
        #pragma unroll
        for (int cidx = 0; cidx < 8; ++cidx) {
            const uint32_t u = s[tid + cidx * 512];
            const bool match = (pass == 0) || (((u ^ prefix) >> hishift) == 0);
            if (match) atomicAdd(&hist[(u >> shift) & 0xFFu], 1u);
        }
        __syncthreads();
        if (tid < 32) {
            uint32_t h[8], sum = 0;
            #pragma unroll
            for (int i = 0; i < 8; ++i) {
                h[i] = hist[255 - (tid * 8 + i)];
                sum += h[i];
            }
            uint32_t inc = sum;
            #pragma unroll
            for (int o = 1; o < 32; o <<= 1) {
                const uint32_t t = __shfl_up_sync(0xffffffffu, inc, o);
                if (tid >= o) inc += t;
            }
            const uint32_t exc = inc - sum;
            if (exc < rank && rank <= inc) {
                uint32_t cum = exc;
                #pragma unroll
                for (int i = 0; i < 8; ++i) {
                    cum += h[i];
                    if (cum >= rank) {
                        sh_sel[0] = prefix | ((uint32_t)(255 - (tid * 8 + i)) << shift);
                        sh_sel[1] = rank - (cum - h[i]);
                        break;
                    }
                }
            }
        }
        __syncthreads();
        prefix = sh_sel[0];
        rank   = sh_sel[1];
        __syncthreads();
    }
    const uint32_t thr_u = prefix;

    float m[8];
    float lmax = 0.0f;
    #pragma unroll
    for (int cidx = 0; cidx < 8; ++cidx) {
        m[cidx] = (su[cidx] > thr_u) ? orig[cidx] : 0.0f;
        lmax = fmaxf(lmax, m[cidx]);
    }
    #pragma unroll
    for (int o = 16; o; o >>= 1)
        lmax = fmaxf(lmax, __shfl_xor_sync(0xffffffffu, lmax, o));
    if ((tid & 31) == 0) red[tid >> 5] = lmax;
    __syncthreads();
    float gmax;
    {
        float v2 = red[tid & 15];
        #pragma unroll
        for (int o = 8; o; o >>= 1)
            v2 = fmaxf(v2, __shfl_xor_sync(0xffffffffu, v2, o));
        gmax = v2;
    }
    __syncthreads();

    float e[8];
    float lsum = 0.0f;
    #pragma unroll
    for (int cidx = 0; cidx < 8; ++cidx) {
        e[cidx] = expf(m[cidx] - gmax);
        lsum += e[cidx];
    }
    #pragma unroll
    for (int o = 16; o; o >>= 1)
        lsum += __shfl_xor_sync(0xffffffffu, lsum, o);
    if ((tid & 31) == 0) red[tid >> 5] = lsum;
    __syncthreads();
    float gsum;
    {
        float v2 = red[tid & 15];
        #pragma unroll
        for (int o = 8; o; o >>= 1)
            v2 += __shfl_xor_sync(0xffffffffu, v2, o);
        gsum = v2;
    }

    const float inv = 1.0f / gsum;
    #pragma unroll
    for (int cidx = 0; cidx < 8; ++cidx) {
        fp16 h, l;
        split_hf(e[cidx] * inv, h, l);
        atthi[(size_t)blockIdx.x * N_TOK + tid + cidx * 512] = h;
        attlo[(size_t)blockIdx.x * N_TOK + tid + cidx * 512] = l;
    }
}

// ---------------------------------------------------------------------------
// Deterministic 8-way split-K reduce (fixed order)
// ---------------------------------------------------------------------------
__global__ void __launch_bounds__(256)
reduce8_kernel(const float4* __restrict__ part, float4* __restrict__ out)
{
    const int i = blockIdx.x * blockDim.x + threadIdx.x;
    const int stride = N_TOK * DDIM / 4;
    float4 o = part[i];
    #pragma unroll
    for (int z = 1; z < 8; ++z) {
        const float4 p = part[(size_t)z * stride + i];
        o.x += p.x; o.y += p.y; o.z += p.z; o.w += p.w;
    }
    out[i] = o;
}

// ---------------------------------------------------------------------------
extern "C" void kernel_launch(void* const* d_in, const int* in_sizes, int n_in,
                              void* d_out, int out_size)
{
    const float* x  = (const float*)d_in[0];
    const float* Wq = (const float*)d_in[1];
    const float* bq = (const float*)d_in[2];
    const float* Wk = (const float*)d_in[3];
    const float* bk = (const float*)d_in[4];
    const float* Wv = (const float*)d_in[5];
    const float* bv = (const float*)d_in[6];
    float* out = (float*)d_out;

    fp16 *xhi, *xlo, *WThi, *qhi, *qlo, *kThi, *vThi, *atthi, *attlo;
    float *k, *v, *score, *part;
    cudaGetSymbolAddress((void**)&xhi,   g_xhi);
    cudaGetSymbolAddress((void**)&xlo,   g_xlo);
    cudaGetSymbolAddress((void**)&WThi,  g_WThi);
    cudaGetSymbolAddress((void**)&qhi,   g_qhi);
    cudaGetSymbolAddress((void**)&qlo,   g_qlo);
    cudaGetSymbolAddress((void**)&kThi,  g_kThi);
    cudaGetSymbolAddress((void**)&vThi,  g_vThi);
    cudaGetSymbolAddress((void**)&atthi, g_atthi);
    cudaGetSymbolAddress((void**)&attlo, g_attlo);
    cudaGetSymbolAddress((void**)&k,     g_k);
    cudaGetSymbolAddress((void**)&v,     g_v);
    cudaGetSymbolAddress((void**)&score, g_score);
    cudaGetSymbolAddress((void**)&part,  g_part);

    cudaFuncSetAttribute(qkv_kernel,
                         cudaFuncAttributeMaxDynamicSharedMemorySize, GEMM_SMEM_BYTES);
    cudaFuncSetAttribute(mma_hf_kernel<false, false>,
                         cudaFuncAttributeMaxDynamicSharedMemorySize, GEMM_SMEM_BYTES);
    cudaFuncSetAttribute(ctx_kernel,
                         cudaFuncAttributeMaxDynamicSharedMemorySize, GEMM_SMEM_BYTES);

    const float inv_sqrt_d = 1.0f / sqrtf((float)DDIM);
    const dim3 tb(32, 8);

    // Pre-split x (A operand: hi+lo); weights transposed, hi only (B operand)
    split_kernel<<<(N_TOK * DDIM) / 256, 256>>>(x, xhi, xlo);
    wt_transpose_kernel<<<dim3(DDIM / 32, DDIM / 32, 3), tb>>>(Wq, Wk, Wv, WThi);

    // QKV merged: grid (4, 32, 3). q pre-split (A of score); k, v f32.
    qkv_kernel<<<dim3(DDIM / 128, N_TOK / 128, 3), 512, GEMM_SMEM_BYTES>>>(
        xhi, xlo, WThi, bq, bk, bv, qhi, qlo, k, v);

    // kT = (k viewed [512][4096])^T hi-only; vT = v^T hi-only (B operands)
    transpose_hi_kernel<<<dim3(N_TOK / 32, DDIM / 32), tb>>>(k, kThi, DDIM, N_TOK);
    transpose_hi_kernel<<<dim3(DDIM / 32, N_TOK / 32), tb>>>(v, vThi, N_TOK, DDIM);

    // Score: M=N=4096, K=512
    mma_hf_kernel<false, false><<<dim3(N_TOK / 128, N_TOK / 128), 512, GEMM_SMEM_BYTES>>>(
        qhi, qlo, DDIM, kThi, DDIM, score, nullptr, nullptr, N_TOK,
        DDIM, nullptr, inv_sqrt_d);

    // Exact top-k + masked softmax; attn pre-split (A of ctx)
    topk_softmax_kernel<<<N_TOK, 512>>>(score, atthi, attlo);

    // Context: split-K=8 (1024 CTAs, ~99% wave util), deterministic reduce
    ctx_kernel<<<dim3(DDIM / 128, N_TOK / 128, 8), 512, GEMM_SMEM_BYTES>>>(
        atthi, attlo, vThi, part);
    reduce8_kernel<<<(N_TOK * DDIM / 4) / 256, 256>>>(
        (const float4*)part, (float4*)out);
}

// round 11
// speedup vs baseline: 3.6378x; 1.6650x over previous
#include <cuda_runtime.h>
#include <cuda_fp16.h>
#include <cstdint>
#include <math.h>

#define N_TOK 4096
#define DDIM  512
#define KEEP  2048

// ---------------- device scratch (uint4 for 16B alignment) ----------------
__device__ uint4 g_xh  [N_TOK * DDIM / 8];
__device__ uint4 g_WTh [3 * DDIM * DDIM / 8];
__device__ uint4 g_qh  [N_TOK * DDIM / 8];
__device__ uint4 g_kTh [N_TOK * DDIM / 8];
__device__ uint4 g_vTh [N_TOK * DDIM / 8];
__device__ uint4 g_atth[(size_t)N_TOK * N_TOK / 8];
__device__ float g_k[N_TOK * DDIM];
__device__ float g_v[N_TOK * DDIM];
__device__ float g_score[(size_t)N_TOK * N_TOK];
__device__ float g_part[8][N_TOK * DDIM];

typedef __half fp16;

// ---------------- helpers ----------------
__device__ __forceinline__ uint32_t smem_u32(const void* p) {
    uint32_t a;
    asm("{ .reg .u64 t; cvta.to.shared.u64 t, %1; cvt.u32.u64 %0, t; }"
        : "=r"(a) : "l"(p));
    return a;
}

#define CP16(dst, src) \
    asm volatile("cp.async.cg.shared.global [%0], [%1], 16;" :: "r"(dst), "l"(src) : "memory")
#define CP_COMMIT() asm volatile("cp.async.commit_group;" ::: "memory")
#define CP_WAIT1()  asm volatile("cp.async.wait_group 1;" ::: "memory")
#define CP_WAIT0()  asm volatile("cp.async.wait_group 0;" ::: "memory")

#define LDSM4(r, a)                                                             \
    asm volatile("ldmatrix.sync.aligned.m8n8.x4.shared.b16 {%0,%1,%2,%3}, [%4];" \
        : "=r"((r)[0]), "=r"((r)[1]), "=r"((r)[2]), "=r"((r)[3]) : "r"(a))

// m16n8k16 fp16 MMA, D += A*B (row.col), f32 accumulate
#define MMA16(cc, a, b)                                                         \
    asm volatile("mma.sync.aligned.m16n8k16.row.col.f32.f16.f16.f32 "           \
        "{%0,%1,%2,%3}, {%4,%5,%6,%7}, {%8,%9}, {%0,%1,%2,%3};"                 \
        : "+f"((cc)[0]), "+f"((cc)[1]), "+f"((cc)[2]), "+f"((cc)[3])            \
        : "r"((a)[0]), "r"((a)[1]), "r"((a)[2]), "r"((a)[3]),                   \
          "r"((b)[0]), "r"((b)[1]))

// ---------------------------------------------------------------------------
// Plain fp16 GEMM body (f32 accum): C = scale*(A @ B^T) (+bias)
// A [M,K], B [N,K] fp16 row-major. Block 128x128, BK=64, 512 threads,
// 16 warps 4x4, warp tile 32x32. Smem: 2 stages x 2 tiles x 128 rows x 144B
// pitch = 73728 B -> 2 CTAs/SM.
// ---------------------------------------------------------------------------
#define TILE_B    18432                    // 128 * 144
#define STAGE_ALL (2 * TILE_B)             // 36864
#define GEMM_SMEM_BYTES (2 * STAGE_ALL)    // 73728

template<bool BIAS, bool HALF_OUT>
__device__ __forceinline__ void gemm_body(
    const fp16* __restrict__ A, int lda,
    const fp16* __restrict__ B, int ldb,
    float* __restrict__ C, fp16* __restrict__ Ch, int ldc,
    int K, const float* __restrict__ bias, float scale,
    int bx, int by, char* sm)
{
    const uint32_t smb = smem_u32(sm);

    const int tid  = threadIdx.x;
    const int w    = tid >> 5;
    const int lane = tid & 31;
    const int wm   = w & 3;
    const int wn   = w >> 2;
    const int g    = lane >> 2;
    const int tig  = lane & 3;

    const int lrow = tid >> 2;
    const int lch  = tid & 3;
    const fp16* pA = A + (size_t)(by * 128 + lrow) * lda + lch * 16;
    const fp16* pB = B + (size_t)(bx * 128 + lrow) * ldb + lch * 16;
    const uint32_t so = (uint32_t)lrow * 144 + lch * 32;

    const int l7 = lane & 7;
    const uint32_t aoff0 = (uint32_t)(wm * 32 + ((lane >> 3) & 1) * 8 + l7) * 144
                         + (uint32_t)(lane >> 4) * 16;
    const uint32_t aoff1 = aoff0 + 16u * 144u;
    const uint32_t boff0 = TILE_B
                         + (uint32_t)(wn * 32 + (lane >> 4) * 8 + l7) * 144
                         + (uint32_t)((lane >> 3) & 1) * 16;
    const uint32_t boff1 = boff0 + 16u * 144u;

    float c[2][4][4] = {};
    const int nT = K >> 6;

    {
        const uint32_t st = smb;
        CP16(st + so,               pA);
        CP16(st + so + 16,          pA + 8);
        CP16(st + TILE_B + so,      pB);
        CP16(st + TILE_B + so + 16, pB + 8);
        CP_COMMIT();
    }

    for (int kt = 0; kt < nT; ++kt) {
        if (kt + 1 < nT) {
            const uint32_t st = smb + ((kt + 1) & 1) * STAGE_ALL;
            const int ko = (kt + 1) * 64;
            CP16(st + so,               pA + ko);
            CP16(st + so + 16,          pA + ko + 8);
            CP16(st + TILE_B + so,      pB + ko);
            CP16(st + TILE_B + so + 16, pB + ko + 8);
            CP_COMMIT();
            CP_WAIT1();
        } else {
            CP_WAIT0();
        }
        __syncthreads();

        const uint32_t stb = smb + (kt & 1) * STAGE_ALL;

        #pragma unroll
        for (int ks = 0; ks < 4; ++ks) {
            const uint32_t koff = (uint32_t)ks * 32;

            uint32_t ah[2][4], bh[2][4];
            LDSM4(ah[0], stb + aoff0 + koff);
            LDSM4(ah[1], stb + aoff1 + koff);
            LDSM4(bh[0], stb + boff0 + koff);
            LDSM4(bh[1], stb + boff1 + koff);

            #pragma unroll
            for (int mi = 0; mi < 2; ++mi)
                #pragma unroll
                for (int ni = 0; ni < 4; ++ni)
                    MMA16(c[mi][ni], ah[mi], bh[ni >> 1] + (ni & 1) * 2);
        }
        __syncthreads();
    }

    #pragma unroll
    for (int mi = 0; mi < 2; ++mi) {
        const int r0 = by * 128 + wm * 32 + mi * 16 + g;
        #pragma unroll
        for (int ni = 0; ni < 4; ++ni) {
            const int col = bx * 128 + wn * 32 + ni * 8 + tig * 2;
            float vv[4];
            vv[0] = c[mi][ni][0] * scale; vv[1] = c[mi][ni][1] * scale;
            vv[2] = c[mi][ni][2] * scale; vv[3] = c[mi][ni][3] * scale;
            if (BIAS) {
                const float b0 = bias[col], b1 = bias[col + 1];
                vv[0] += b0; vv[1] += b1; vv[2] += b0; vv[3] += b1;
            }
            if (HALF_OUT) {
                __half2 t2;
                t2.x = __float2half_rn(vv[0]); t2.y = __float2half_rn(vv[1]);
                *reinterpret_cast<__half2*>(Ch + (size_t)r0 * ldc + col) = t2;
                t2.x = __float2half_rn(vv[2]); t2.y = __float2half_rn(vv[3]);
                *reinterpret_cast<__half2*>(Ch + (size_t)(r0 + 8) * ldc + col) = t2;
            } else {
                *reinterpret_cast<float2*>(C + (size_t)r0 * ldc + col)       = make_float2(vv[0], vv[1]);
                *reinterpret_cast<float2*>(C + (size_t)(r0 + 8) * ldc + col) = make_float2(vv[2], vv[3]);
            }
        }
    }
}

template<bool BIAS, bool HALF_OUT>
__global__ void __launch_bounds__(512, 2)
mma_hf_kernel(const fp16* __restrict__ A, int lda,
              const fp16* __restrict__ B, int ldb,
              float* __restrict__ C, fp16* __restrict__ Ch,
              int ldc, int K, const float* __restrict__ bias, float scale)
{
    extern __shared__ char sm[];
    gemm_body<BIAS, HALF_OUT>(A, lda, B, ldb, C, Ch, ldc,
                              K, bias, scale, blockIdx.x, blockIdx.y, sm);
}

// Merged QKV: grid (4, 32, 3); z=0 -> q (fp16 out), z=1 -> k, z=2 -> v (f32)
__global__ void __launch_bounds__(512, 2)
qkv_kernel(const fp16* __restrict__ xh, const fp16* __restrict__ WTh,
           const float* __restrict__ bq, const float* __restrict__ bk,
           const float* __restrict__ bv,
           fp16* __restrict__ qh, float* __restrict__ k, float* __restrict__ v)
{
    extern __shared__ char sm[];
    const int z = blockIdx.z;
    const fp16* Wh = WTh + (size_t)z * DDIM * DDIM;
    if (z == 0)
        gemm_body<true, true>(xh, DDIM, Wh, DDIM, nullptr, qh,
                              DDIM, DDIM, bq, 1.0f, blockIdx.x, blockIdx.y, sm);
    else if (z == 1)
        gemm_body<true, false>(xh, DDIM, Wh, DDIM, k, nullptr,
                               DDIM, DDIM, bk, 1.0f, blockIdx.x, blockIdx.y, sm);
    else
        gemm_body<true, false>(xh, DDIM, Wh, DDIM, v, nullptr,
                               DDIM, DDIM, bv, 1.0f, blockIdx.x, blockIdx.y, sm);
}

// Merged context split-K=8: grid (4, 32, 8)
__global__ void __launch_bounds__(512, 2)
ctx_kernel(const fp16* __restrict__ atth, const fp16* __restrict__ vTh,
           float* __restrict__ part)
{
    extern __shared__ char sm[];
    const int z = blockIdx.z;
    gemm_body<false, false>(atth + z * (N_TOK / 8), N_TOK,
                            vTh + z * (N_TOK / 8), N_TOK,
                            part + (size_t)z * N_TOK * DDIM, nullptr, DDIM,
                            N_TOK / 8, nullptr, 1.0f, blockIdx.x, blockIdx.y, sm);
}

// ---------------------------------------------------------------------------
// Elementwise f32 -> fp16 convert
// ---------------------------------------------------------------------------
__global__ void __launch_bounds__(256)
cvt_kernel(const float* __restrict__ in, fp16* __restrict__ outp)
{
    const int i = blockIdx.x * blockDim.x + threadIdx.x;
    outp[i] = __float2half_rn(in[i]);
}

// ---------------------------------------------------------------------------
// 32x32 tiled transpose, f32 in -> fp16 out. Merged 3 weights via grid.z.
// ---------------------------------------------------------------------------
__device__ __forceinline__ void transpose_hi_body(
    const float* __restrict__ in, fp16* __restrict__ hi, int R, int C)
{
    __shared__ float t[32][33];
    const int bx = blockIdx.x * 32, by = blockIdx.y * 32;
    const int tx = threadIdx.x, ty = threadIdx.y;
    #pragma unroll
    for (int j = 0; j < 32; j += 8)
        t[ty + j][tx] = in[(size_t)(by + ty + j) * C + bx + tx];
    __syncthreads();
    #pragma unroll
    for (int j = 0; j < 32; j += 8)
        hi[(size_t)(bx + ty + j) * R + by + tx] = __float2half_rn(t[tx][ty + j]);
}

__global__ void __launch_bounds__(256)
transpose_hi_kernel(const float* __restrict__ in, fp16* __restrict__ hi, int R, int C)
{
    transpose_hi_body(in, hi, R, C);
}

__global__ void __launch_bounds__(256)
wt_transpose_kernel(const float* __restrict__ Wq, const float* __restrict__ Wk,
                    const float* __restrict__ Wv, fp16* __restrict__ hi)
{
    const int z = blockIdx.z;
    const float* in = (z == 0) ? Wq : (z == 1) ? Wk : Wv;
    transpose_hi_body(in, hi + (size_t)z * DDIM * DDIM, DDIM, DDIM);
}

// ---------------------------------------------------------------------------
// Exact per-row top-k (4-pass radix select, plain smem atomics) +
// masked softmax; emits attn as fp16. One block (512 thr)/row.
// ---------------------------------------------------------------------------
__global__ void __launch_bounds__(512)
topk_softmax_kernel(const float* __restrict__ score, fp16* __restrict__ atth)
{
    __shared__ uint32_t s[N_TOK];
    __shared__ uint32_t hist[256];
    __shared__ uint32_t sh_sel[2];
    __shared__ float red[16];

    const int tid = threadIdx.x;
    const float* row = score + (size_t)blockIdx.x * N_TOK;

    float orig[8];
    uint32_t su[8];
    #pragma unroll
    for (int cidx = 0; cidx < 8; ++cidx) {
        const float f = row[tid + cidx * 512];
        orig[cidx] = f;
        uint32_t u = __float_as_uint(f);
        u ^= (uint32_t)(((int32_t)u) >> 31) | 0x80000000u;
        su[cidx] = u;
        s[tid + cidx * 512] = u;
    }

    uint32_t prefix = 0, rank = KEEP;
    #pragma unroll
    for (int pass = 0; pass < 4; ++pass) {
        const int shift   = 24 - pass * 8;
        const int hishift = (pass == 0) ? 0 : (shift + 8);
        if (tid < 256) hist[tid] = 0;
        __syncthreads();
        #pragma unroll
        for (int cidx = 0; cidx < 8; ++cidx) {
            const uint32_t u = s[tid + cidx * 512];
            const bool match = (pass == 0) || (((u ^ prefix) >> hishift) == 0);
            if (match) atomicAdd(&hist[(u >> shift) & 0xFFu], 1u);
        }
        __syncthreads();
        if (tid < 32) {
            uint32_t h[8], sum = 0;
            #pragma unroll
            for (int i = 0; i < 8; ++i) {
                h[i] = hist[255 - (tid * 8 + i)];
                sum += h[i];
            }
            uint32_t inc = sum;
            #pragma unroll
            for (int o = 1; o < 32; o <<= 1) {
                const uint32_t t = __shfl_up_sync(0xffffffffu, inc, o);
                if (tid >= o) inc += t;
            }
            const uint32_t exc = inc - sum;
            if (exc < rank && rank <= inc) {
                uint32_t cum = exc;
                #pragma unroll
                for (int i = 0; i < 8; ++i) {
                    cum += h[i];
                    if (cum >= rank) {
                        sh_sel[0] = prefix | ((uint32_t)(255 - (tid * 8 + i)) << shift);
                        sh_sel[1] = rank - (cum - h[i]);
                        break;
                    }
                }
            }
        }
        __syncthreads();
        prefix = sh_sel[0];
        rank   = sh_sel[1];
        __syncthreads();
    }
    const uint32_t thr_u = prefix;

    float m[8];
    float lmax = 0.0f;
    #pragma unroll
    for (int cidx = 0; cidx < 8; ++cidx) {
        m[cidx] = (su[cidx] > thr_u) ? orig[cidx] : 0.0f;
        lmax = fmaxf(lmax, m[cidx]);
    }
    #pragma unroll
    for (int o = 16; o; o >>= 1)
        lmax = fmaxf(lmax, __shfl_xor_sync(0xffffffffu, lmax, o));
    if ((tid & 31) == 0) red[tid >> 5] = lmax;
    __syncthreads();
    float gmax;
    {
        float v2 = red[tid & 15];
        #pragma unroll
        for (int o = 8; o; o >>= 1)
            v2 = fmaxf(v2, __shfl_xor_sync(0xffffffffu, v2, o));
        gmax = v2;
    }
    __syncthreads();

    float e[8];
    float lsum = 0.0f;
    #pragma unroll
    for (int cidx = 0; cidx < 8; ++cidx) {
        e[cidx] = expf(m[cidx] - gmax);
        lsum += e[cidx];
    }
    #pragma unroll
    for (int o = 16; o; o >>= 1)
        lsum += __shfl_xor_sync(0xffffffffu, lsum, o);
    if ((tid & 31) == 0) red[tid >> 5] = lsum;
    __syncthreads();
    float gsum;
    {
        float v2 = red[tid & 15];
        #pragma unroll
        for (int o = 8; o; o >>= 1)
            v2 += __shfl_xor_sync(0xffffffffu, v2, o);
        gsum = v2;
    }

    const float inv = 1.0f / gsum;
    #pragma unroll
    for (int cidx = 0; cidx < 8; ++cidx)
        atth[(size_t)blockIdx.x * N_TOK + tid + cidx * 512] =
            __float2half_rn(e[cidx] * inv);
}

// ---------------------------------------------------------------------------
// Deterministic 8-way split-K reduce (fixed order)
// ---------------------------------------------------------------------------
__global__ void __launch_bounds__(256)
reduce8_kernel(const float4* __restrict__ part, float4* __restrict__ out)
{
    const int i = blockIdx.x * blockDim.x + threadIdx.x;
    const int stride = N_TOK * DDIM / 4;
    float4 o = part[i];
    #pragma unroll
    for (int z = 1; z < 8; ++z) {
        const float4 p = part[(size_t)z * stride + i];
        o.x += p.x; o.y += p.y; o.z += p.z; o.w += p.w;
    }
    out[i] = o;
}

// ---------------------------------------------------------------------------
extern "C" void kernel_launch(void* const* d_in, const int* in_sizes, int n_in,
                              void* d_out, int out_size)
{
    const float* x  = (const float*)d_in[0];
    const float* Wq = (const float*)d_in[1];
    const float* bq = (const float*)d_in[2];
    const float* Wk = (const float*)d_in[3];
    const float* bk = (const float*)d_in[4];
    const float* Wv = (const float*)d_in[5];
    const float* bv = (const float*)d_in[6];
    float* out = (float*)d_out;

    fp16 *xh, *WTh, *qh, *kTh, *vTh, *atth;
    float *k, *v, *score, *part;
    cudaGetSymbolAddress((void**)&xh,   g_xh);
    cudaGetSymbolAddress((void**)&WTh,  g_WTh);
    cudaGetSymbolAddress((void**)&qh,   g_qh);
    cudaGetSymbolAddress((void**)&kTh,  g_kTh);
    cudaGetSymbolAddress((void**)&vTh,  g_vTh);
    cudaGetSymbolAddress((void**)&atth, g_atth);
    cudaGetSymbolAddress((void**)&k,    g_k);
    cudaGetSymbolAddress((void**)&v,    g_v);
    cudaGetSymbolAddress((void**)&score, g_score);
    cudaGetSymbolAddress((void**)&part,  g_part);

    cudaFuncSetAttribute(qkv_kernel,
                         cudaFuncAttributeMaxDynamicSharedMemorySize, GEMM_SMEM_BYTES);
    cudaFuncSetAttribute(mma_hf_kernel<false, false>,
                         cudaFuncAttributeMaxDynamicSharedMemorySize, GEMM_SMEM_BYTES);
    cudaFuncSetAttribute(ctx_kernel,
                         cudaFuncAttributeMaxDynamicSharedMemorySize, GEMM_SMEM_BYTES);

    const float inv_sqrt_d = 1.0f / sqrtf((float)DDIM);
    const dim3 tb(32, 8);

    // x -> fp16; weights transposed -> fp16
    cvt_kernel<<<(N_TOK * DDIM) / 256, 256>>>(x, xh);
    wt_transpose_kernel<<<dim3(DDIM / 32, DDIM / 32, 3), tb>>>(Wq, Wk, Wv, WTh);

    // QKV merged: grid (4, 32, 3). q fp16; k, v f32.
    qkv_kernel<<<dim3(DDIM / 128, N_TOK / 128, 3), 512, GEMM_SMEM_BYTES>>>(
        xh, WTh, bq, bk, bv, qh, k, v);

    // kT = (k viewed [512][4096])^T fp16; vT = v^T fp16
    transpose_hi_kernel<<<dim3(N_TOK / 32, DDIM / 32), tb>>>(k, kTh, DDIM, N_TOK);
    transpose_hi_kernel<<<dim3(DDIM / 32, N_TOK / 32), tb>>>(v, vTh, N_TOK, DDIM);

    // Score: M=N=4096, K=512
    mma_hf_kernel<false, false><<<dim3(N_TOK / 128, N_TOK / 128), 512, GEMM_SMEM_BYTES>>>(
        qh, DDIM, kTh, DDIM, score, nullptr, N_TOK, DDIM, nullptr, inv_sqrt_d);

    // Exact top-k + masked softmax; attn -> fp16
    topk_softmax_kernel<<<N_TOK, 512>>>(score, atth);

    // Context: split-K=8 (1024 CTAs), deterministic reduce
    ctx_kernel<<<dim3(DDIM / 128, N_TOK / 128, 8), 512, GEMM_SMEM_BYTES>>>(
        atth, vTh, part);
    reduce8_kernel<<<(N_TOK * DDIM / 4) / 256, 256>>>(
        (const float4*)part, (float4*)out);
}

// round 13
// speedup vs baseline: 3.9078x; 1.0742x over previous
#include <cuda_runtime.h>
#include <cuda_fp16.h>
#include <cstdint>
#include <math.h>

#define N_TOK 4096
#define DDIM  512
#define KEEP  2048

// ---------------- device scratch (uint4 for 16B alignment) ----------------
__device__ uint4 g_xh  [N_TOK * DDIM / 8];
__device__ uint4 g_WTh [3 * DDIM * DDIM / 8];
__device__ uint4 g_qh  [N_TOK * DDIM / 8];
__device__ uint4 g_kTh [N_TOK * DDIM / 8];
__device__ uint4 g_vTh [N_TOK * DDIM / 8];
__device__ uint4 g_scoreh[(size_t)N_TOK * N_TOK / 8];
__device__ uint4 g_atth  [(size_t)N_TOK * N_TOK / 8];
__device__ uint4 g_parth [8 * (size_t)N_TOK * DDIM / 8];
__device__ float g_k[N_TOK * DDIM];
__device__ float g_v[N_TOK * DDIM];

typedef __half fp16;

// ---------------- helpers ----------------
__device__ __forceinline__ uint32_t smem_u32(const void* p) {
    uint32_t a;
    asm("{ .reg .u64 t; cvta.to.shared.u64 t, %1; cvt.u32.u64 %0, t; }"
        : "=r"(a) : "l"(p));
    return a;
}

#define CP16(dst, src) \
    asm volatile("cp.async.cg.shared.global [%0], [%1], 16;" :: "r"(dst), "l"(src) : "memory")
#define CP_COMMIT() asm volatile("cp.async.commit_group;" ::: "memory")
#define CP_WAIT1()  asm volatile("cp.async.wait_group 1;" ::: "memory")
#define CP_WAIT0()  asm volatile("cp.async.wait_group 0;" ::: "memory")

#define LDSM4(r, a)                                                             \
    asm volatile("ldmatrix.sync.aligned.m8n8.x4.shared.b16 {%0,%1,%2,%3}, [%4];" \
        : "=r"((r)[0]), "=r"((r)[1]), "=r"((r)[2]), "=r"((r)[3]) : "r"(a))

// m16n8k16 fp16 MMA, D += A*B (row.col), f32 accumulate
#define MMA16(cc, a, b)                                                         \
    asm volatile("mma.sync.aligned.m16n8k16.row.col.f32.f16.f16.f32 "           \
        "{%0,%1,%2,%3}, {%4,%5,%6,%7}, {%8,%9}, {%0,%1,%2,%3};"                 \
        : "+f"((cc)[0]), "+f"((cc)[1]), "+f"((cc)[2]), "+f"((cc)[3])            \
        : "r"((a)[0]), "r"((a)[1]), "r"((a)[2]), "r"((a)[3]),                   \
          "r"((b)[0]), "r"((b)[1]))

// ---------------------------------------------------------------------------
// Plain fp16 GEMM body (f32 accum): C = scale*(A @ B^T) (+bias)
// Block 128x128, BK=64, 512 threads, 16 warps 4x4, warp tile 32x32.
// Smem: 2 stages x 2 tiles x 128 rows x 144B pitch = 73728 B -> 2 CTAs/SM.
// ---------------------------------------------------------------------------
#define TILE_B    18432
#define STAGE_ALL (2 * TILE_B)
#define GEMM_SMEM_BYTES (2 * STAGE_ALL)    // 73728

template<bool BIAS, bool HALF_OUT>
__device__ __forceinline__ void gemm_body(
    const fp16* __restrict__ A, int lda,
    const fp16* __restrict__ B, int ldb,
    float* __restrict__ C, fp16* __restrict__ Ch, int ldc,
    int K, const float* __restrict__ bias, float scale,
    int bx, int by, char* sm)
{
    const uint32_t smb = smem_u32(sm);

    const int tid  = threadIdx.x;
    const int w    = tid >> 5;
    const int lane = tid & 31;
    const int wm   = w & 3;
    const int wn   = w >> 2;
    const int g    = lane >> 2;
    const int tig  = lane & 3;

    const int lrow = tid >> 2;
    const int lch  = tid & 3;
    const fp16* pA = A + (size_t)(by * 128 + lrow) * lda + lch * 16;
    const fp16* pB = B + (size_t)(bx * 128 + lrow) * ldb + lch * 16;
    const uint32_t so = (uint32_t)lrow * 144 + lch * 32;

    const int l7 = lane & 7;
    const uint32_t aoff0 = (uint32_t)(wm * 32 + ((lane >> 3) & 1) * 8 + l7) * 144
                         + (uint32_t)(lane >> 4) * 16;
    const uint32_t aoff1 = aoff0 + 16u * 144u;
    const uint32_t boff0 = TILE_B
                         + (uint32_t)(wn * 32 + (lane >> 4) * 8 + l7) * 144
                         + (uint32_t)((lane >> 3) & 1) * 16;
    const uint32_t boff1 = boff0 + 16u * 144u;

    float c[2][4][4] = {};
    const int nT = K >> 6;

    {
        const uint32_t st = smb;
        CP16(st + so,               pA);
        CP16(st + so + 16,          pA + 8);
        CP16(st + TILE_B + so,      pB);
        CP16(st + TILE_B + so + 16, pB + 8);
        CP_COMMIT();
    }

    for (int kt = 0; kt < nT; ++kt) {
        if (kt + 1 < nT) {
            const uint32_t st = smb + ((kt + 1) & 1) * STAGE_ALL;
            const int ko = (kt + 1) * 64;
            CP16(st + so,               pA + ko);
            CP16(st + so + 16,          pA + ko + 8);
            CP16(st + TILE_B + so,      pB + ko);
            CP16(st + TILE_B + so + 16, pB + ko + 8);
            CP_COMMIT();
            CP_WAIT1();
        } else {
            CP_WAIT0();
        }
        __syncthreads();

        const uint32_t stb = smb + (kt & 1) * STAGE_ALL;

        #pragma unroll
        for (int ks = 0; ks < 4; ++ks) {
            const uint32_t koff = (uint32_t)ks * 32;

            uint32_t ah[2][4], bh[2][4];
            LDSM4(ah[0], stb + aoff0 + koff);
            LDSM4(ah[1], stb + aoff1 + koff);
            LDSM4(bh[0], stb + boff0 + koff);
            LDSM4(bh[1], stb + boff1 + koff);

            #pragma unroll
            for (int mi = 0; mi < 2; ++mi)
                #pragma unroll
                for (int ni = 0; ni < 4; ++ni)
                    MMA16(c[mi][ni], ah[mi], bh[ni >> 1] + (ni & 1) * 2);
        }
        __syncthreads();
    }

    #pragma unroll
    for (int mi = 0; mi < 2; ++mi) {
        const int r0 = by * 128 + wm * 32 + mi * 16 + g;
        #pragma unroll
        for (int ni = 0; ni < 4; ++ni) {
            const int col = bx * 128 + wn * 32 + ni * 8 + tig * 2;
            float vv[4];
            vv[0] = c[mi][ni][0] * scale; vv[1] = c[mi][ni][1] * scale;
            vv[2] = c[mi][ni][2] * scale; vv[3] = c[mi][ni][3] * scale;
            if (BIAS) {
                const float b0 = bias[col], b1 = bias[col + 1];
                vv[0] += b0; vv[1] += b1; vv[2] += b0; vv[3] += b1;
            }
            if (HALF_OUT) {
                __half2 t2;
                t2.x = __float2half_rn(vv[0]); t2.y = __float2half_rn(vv[1]);
                *reinterpret_cast<__half2*>(Ch + (size_t)r0 * ldc + col) = t2;
                t2.x = __float2half_rn(vv[2]); t2.y = __float2half_rn(vv[3]);
                *reinterpret_cast<__half2*>(Ch + (size_t)(r0 + 8) * ldc + col) = t2;
            } else {
                *reinterpret_cast<float2*>(C + (size_t)r0 * ldc + col)       = make_float2(vv[0], vv[1]);
                *reinterpret_cast<float2*>(C + (size_t)(r0 + 8) * ldc + col) = make_float2(vv[2], vv[3]);
            }
        }
    }
}

template<bool BIAS, bool HALF_OUT>
__global__ void __launch_bounds__(512, 2)
mma_hf_kernel(const fp16* __restrict__ A, int lda,
              const fp16* __restrict__ B, int ldb,
              float* __restrict__ C, fp16* __restrict__ Ch,
              int ldc, int K, const float* __restrict__ bias, float scale)
{
    extern __shared__ char sm[];
    gemm_body<BIAS, HALF_OUT>(A, lda, B, ldb, C, Ch, ldc,
                              K, bias, scale, blockIdx.x, blockIdx.y, sm);
}

// Merged QKV: grid (4, 32, 3); z=0 -> q (fp16 out), z=1 -> k, z=2 -> v (f32)
__global__ void __launch_bounds__(512, 2)
qkv_kernel(const fp16* __restrict__ xh, const fp16* __restrict__ WTh,
           const float* __restrict__ bq, const float* __restrict__ bk,
           const float* __restrict__ bv,
           fp16* __restrict__ qh, float* __restrict__ k, float* __restrict__ v)
{
    extern __shared__ char sm[];
    const int z = blockIdx.z;
    const fp16* Wh = WTh + (size_t)z * DDIM * DDIM;
    if (z == 0)
        gemm_body<true, true>(xh, DDIM, Wh, DDIM, nullptr, qh,
                              DDIM, DDIM, bq, 1.0f, blockIdx.x, blockIdx.y, sm);
    else if (z == 1)
        gemm_body<true, false>(xh, DDIM, Wh, DDIM, k, nullptr,
                               DDIM, DDIM, bk, 1.0f, blockIdx.x, blockIdx.y, sm);
    else
        gemm_body<true, false>(xh, DDIM, Wh, DDIM, v, nullptr,
                               DDIM, DDIM, bv, 1.0f, blockIdx.x, blockIdx.y, sm);
}

// Merged context split-K=8: grid (4, 32, 8); partials in fp16
__global__ void __launch_bounds__(512, 2)
ctx_kernel(const fp16* __restrict__ atth, const fp16* __restrict__ vTh,
           fp16* __restrict__ parth)
{
    extern __shared__ char sm[];
    const int z = blockIdx.z;
    gemm_body<false, true>(atth + z * (N_TOK / 8), N_TOK,
                           vTh + z * (N_TOK / 8), N_TOK,
                           nullptr, parth + (size_t)z * N_TOK * DDIM, DDIM,
                           N_TOK / 8, nullptr, 1.0f, blockIdx.x, blockIdx.y, sm);
}

// ---------------------------------------------------------------------------
// Elementwise f32 -> fp16 convert
// ---------------------------------------------------------------------------
__global__ void __launch_bounds__(256)
cvt_kernel(const float* __restrict__ in, fp16* __restrict__ outp)
{
    const int i = blockIdx.x * blockDim.x + threadIdx.x;
    outp[i] = __float2half_rn(in[i]);
}

// ---------------------------------------------------------------------------
// 32x32 tiled transpose, f32 in -> fp16 out. Merged 3 weights via grid.z.
// ---------------------------------------------------------------------------
__device__ __forceinline__ void transpose_hi_body(
    const float* __restrict__ in, fp16* __restrict__ hi, int R, int C)
{
    __shared__ float t[32][33];
    const int bx = blockIdx.x * 32, by = blockIdx.y * 32;
    const int tx = threadIdx.x, ty = threadIdx.y;
    #pragma unroll
    for (int j = 0; j < 32; j += 8)
        t[ty + j][tx] = in[(size_t)(by + ty + j) * C + bx + tx];
    __syncthreads();
    #pragma unroll
    for (int j = 0; j < 32; j += 8)
        hi[(size_t)(bx + ty + j) * R + by + tx] = __float2half_rn(t[tx][ty + j]);
}

__global__ void __launch_bounds__(256)
transpose_hi_kernel(const float* __restrict__ in, fp16* __restrict__ hi, int R, int C)
{
    transpose_hi_body(in, hi, R, C);
}

__global__ void __launch_bounds__(256)
wt_transpose_kernel(const float* __restrict__ Wq, const float* __restrict__ Wk,
                    const float* __restrict__ Wv, fp16* __restrict__ hi)
{
    const int z = blockIdx.z;
    const float* in = (z == 0) ? Wq : (z == 1) ? Wk : Wv;
    transpose_hi_body(in, hi + (size_t)z * DDIM * DDIM, DDIM, DDIM);
}

// ---------------------------------------------------------------------------
// Exact per-row top-k on fp16 scores: 2-pass radix select on 16-bit
// order-preserving keys (u = bits ^ (sign ? 0xFFFF : 0x8000)), then masked
// softmax (f32) emitting fp16 attn. One block (512 thr)/row; each thread owns
// 8 consecutive values (one uint4) — keys stay in registers across passes.
// ---------------------------------------------------------------------------
__global__ void __launch_bounds__(512)
topk_softmax_kernel(const fp16* __restrict__ scoreh, fp16* __restrict__ atth)
{
    __shared__ uint32_t hist[256];
    __shared__ uint32_t sh_sel[2];
    __shared__ float red[16];

    const int tid = threadIdx.x;
    const uint4* rowv = reinterpret_cast<const uint4*>(scoreh + (size_t)blockIdx.x * N_TOK);
    const uint4 pk = rowv[tid];

    // unpack 8 halves: values (f32) + transformed 16-bit keys
    float orig[8];
    uint32_t su[8];
    {
        const uint32_t wds[4] = {pk.x, pk.y, pk.z, pk.w};
        #pragma unroll
        for (int j = 0; j < 4; ++j) {
            const uint32_t x = wds[j];
            // per-lane: sign? ^0xFFFF : ^0x8000
            const uint32_t xr = x ^ (0x80008000u | (((x >> 15) & 0x00010001u) * 0x7FFFu));
            su[2 * j + 0] = xr & 0xFFFFu;
            su[2 * j + 1] = xr >> 16;
            const float2 f2 = __half22float2(*reinterpret_cast<const __half2*>(&x));
            orig[2 * j + 0] = f2.x;
            orig[2 * j + 1] = f2.y;
        }
    }

    uint32_t prefix = 0, rank = KEEP;
    #pragma unroll
    for (int pass = 0; pass < 2; ++pass) {
        const int shift = 8 - pass * 8;
        if (tid < 256) hist[tid] = 0;
        __syncthreads();
        #pragma unroll
        for (int j = 0; j < 8; ++j) {
            const uint32_t u = su[j];
            const bool match = (pass == 0) || ((u >> 8) == (prefix >> 8));
            if (match) atomicAdd(&hist[(u >> shift) & 0xFFu], 1u);
        }
        __syncthreads();
        if (tid < 32) {
            uint32_t h[8], sum = 0;
            #pragma unroll
            for (int i = 0; i < 8; ++i) {
                h[i] = hist[255 - (tid * 8 + i)];
                sum += h[i];
            }
            uint32_t inc = sum;
            #pragma unroll
            for (int o = 1; o < 32; o <<= 1) {
                const uint32_t t = __shfl_up_sync(0xffffffffu, inc, o);
                if (tid >= o) inc += t;
            }
            const uint32_t exc = inc - sum;
            if (exc < rank && rank <= inc) {
                uint32_t cum = exc;
                #pragma unroll
                for (int i = 0; i < 8; ++i) {
                    cum += h[i];
                    if (cum >= rank) {
                        sh_sel[0] = prefix | ((uint32_t)(255 - (tid * 8 + i)) << shift);
                        sh_sel[1] = rank - (cum - h[i]);
                        break;
                    }
                }
            }
        }
        __syncthreads();
        prefix = sh_sel[0];
        rank   = sh_sel[1];
        __syncthreads();
    }
    const uint32_t thr_u = prefix;   // exact KEEP-th largest 16-bit key

    float m[8];
    float lmax = 0.0f;
    #pragma unroll
    for (int j = 0; j < 8; ++j) {
        m[j] = (su[j] > thr_u) ? orig[j] : 0.0f;
        lmax = fmaxf(lmax, m[j]);
    }
    #pragma unroll
    for (int o = 16; o; o >>= 1)
        lmax = fmaxf(lmax, __shfl_xor_sync(0xffffffffu, lmax, o));
    if ((tid & 31) == 0) red[tid >> 5] = lmax;
    __syncthreads();
    float gmax;
    {
        float v2 = red[tid & 15];
        #pragma unroll
        for (int o = 8; o; o >>= 1)
            v2 = fmaxf(v2, __shfl_xor_sync(0xffffffffu, v2, o));
        gmax = v2;
    }
    __syncthreads();

    float e[8];
    float lsum = 0.0f;
    #pragma unroll
    for (int j = 0; j < 8; ++j) {
        e[j] = expf(m[j] - gmax);
        lsum += e[j];
    }
    #pragma unroll
    for (int o = 16; o; o >>= 1)
        lsum += __shfl_xor_sync(0xffffffffu, lsum, o);
    if ((tid & 31) == 0) red[tid >> 5] = lsum;
    __syncthreads();
    float gsum;
    {
        float v2 = red[tid & 15];
        #pragma unroll
        for (int o = 8; o; o >>= 1)
            v2 += __shfl_xor_sync(0xffffffffu, v2, o);
        gsum = v2;
    }

    const float inv = 1.0f / gsum;
    uint4 outp;
    uint32_t* ow = reinterpret_cast<uint32_t*>(&outp);
    #pragma unroll
    for (int j = 0; j < 4; ++j) {
        __half2 h2;
        h2.x = __float2half_rn(e[2 * j + 0] * inv);
        h2.y = __float2half_rn(e[2 * j + 1] * inv);
        ow[j] = *reinterpret_cast<uint32_t*>(&h2);
    }
    reinterpret_cast<uint4*>(atth + (size_t)blockIdx.x * N_TOK)[tid] = outp;
}

// ---------------------------------------------------------------------------
// Deterministic 8-way split-K reduce: fp16 partials -> f32 out (fixed order)
// ---------------------------------------------------------------------------
__global__ void __launch_bounds__(256)
reduce8_kernel(const uint4* __restrict__ parth, float4* __restrict__ out)
{
    const int i = blockIdx.x * blockDim.x + threadIdx.x;   // 8 halves per thread
    const size_t stride = (size_t)N_TOK * DDIM / 8;
    float acc[8] = {};
    #pragma unroll
    for (int z = 0; z < 8; ++z) {
        const uint4 p = parth[(size_t)z * stride + i];
        const uint32_t wds[4] = {p.x, p.y, p.z, p.w};
        #pragma unroll
        for (int j = 0; j < 4; ++j) {
            const float2 f = __half22float2(*reinterpret_cast<const __half2*>(&wds[j]));
            acc[2 * j]     += f.x;
            acc[2 * j + 1] += f.y;
        }
    }
    out[2 * i]     = make_float4(acc[0], acc[1], acc[2], acc[3]);
    out[2 * i + 1] = make_float4(acc[4], acc[5], acc[6], acc[7]);
}

// ---------------------------------------------------------------------------
extern "C" void kernel_launch(void* const* d_in, const int* in_sizes, int n_in,
                              void* d_out, int out_size)
{
    const float* x  = (const float*)d_in[0];
    const float* Wq = (const float*)d_in[1];
    const float* bq = (const float*)d_in[2];
    const float* Wk = (const float*)d_in[3];
    const float* bk = (const float*)d_in[4];
    const float* Wv = (const float*)d_in[5];
    const float* bv = (const float*)d_in[6];
    float* out = (float*)d_out;

    fp16 *xh, *WTh, *qh, *kTh, *vTh, *scoreh, *atth, *parth;
    float *k, *v;
    cudaGetSymbolAddress((void**)&xh,     g_xh);
    cudaGetSymbolAddress((void**)&WTh,    g_WTh);
    cudaGetSymbolAddress((void**)&qh,     g_qh);
    cudaGetSymbolAddress((void**)&kTh,    g_kTh);
    cudaGetSymbolAddress((void**)&vTh,    g_vTh);
    cudaGetSymbolAddress((void**)&scoreh, g_scoreh);
    cudaGetSymbolAddress((void**)&atth,   g_atth);
    cudaGetSymbolAddress((void**)&parth,  g_parth);
    cudaGetSymbolAddress((void**)&k,      g_k);
    cudaGetSymbolAddress((void**)&v,      g_v);

    cudaFuncSetAttribute(qkv_kernel,
                         cudaFuncAttributeMaxDynamicSharedMemorySize, GEMM_SMEM_BYTES);
    cudaFuncSetAttribute(mma_hf_kernel<false, true>,
                         cudaFuncAttributeMaxDynamicSharedMemorySize, GEMM_SMEM_BYTES);
    cudaFuncSetAttribute(ctx_kernel,
                         cudaFuncAttributeMaxDynamicSharedMemorySize, GEMM_SMEM_BYTES);

    const float inv_sqrt_d = 1.0f / sqrtf((float)DDIM);
    const dim3 tb(32, 8);

    // x -> fp16; weights transposed -> fp16
    cvt_kernel<<<(N_TOK * DDIM) / 256, 256>>>(x, xh);
    wt_transpose_kernel<<<dim3(DDIM / 32, DDIM / 32, 3), tb>>>(Wq, Wk, Wv, WTh);

    // QKV merged: grid (4, 32, 3). q fp16; k, v f32.
    qkv_kernel<<<dim3(DDIM / 128, N_TOK / 128, 3), 512, GEMM_SMEM_BYTES>>>(
        xh, WTh, bq, bk, bv, qh, k, v);

    // kT = (k viewed [512][4096])^T fp16; vT = v^T fp16
    transpose_hi_kernel<<<dim3(N_TOK / 32, DDIM / 32), tb>>>(k, kTh, DDIM, N_TOK);
    transpose_hi_kernel<<<dim3(DDIM / 32, N_TOK / 32), tb>>>(v, vTh, N_TOK, DDIM);

    // Score: M=N=4096, K=512 -> fp16 (scaled)
    mma_hf_kernel<false, true><<<dim3(N_TOK / 128, N_TOK / 128), 512, GEMM_SMEM_BYTES>>>(
        qh, DDIM, kTh, DDIM, nullptr, scoreh, N_TOK, DDIM, nullptr, inv_sqrt_d);

    // Exact top-k (2-pass, fp16 keys) + masked softmax -> fp16 attn
    topk_softmax_kernel<<<N_TOK, 512>>>(scoreh, atth);

    // Context: split-K=8, fp16 partials, deterministic f32 reduce
    ctx_kernel<<<dim3(DDIM / 128, N_TOK / 128, 8), 512, GEMM_SMEM_BYTES>>>(
        atth, vTh, parth);
    reduce8_kernel<<<(N_TOK * DDIM / 8) / 256, 256>>>(
        (const uint4*)parth, (float4*)out);
}